// round 1
// baseline (speedup 1.0000x reference)
#include <cuda_runtime.h>
#include <cuda_bf16.h>

// Problem constants
#define Bv 4
#define Sv 2048
#define Ev 512
#define Hv 8
#define HEv 4096            // H*E
#define EEv 262144          // E*E

// ---------------- scratch (static device globals; no allocation) ----------------
__device__ float g_G[(long)Bv * EEv];        // 4 MB  : G_b = k_b^T v_b
__device__ float g_T[(long)Bv * Hv * EEv];   // 32 MB : T1 then reused as T3s [B][E][H*E]
__device__ float g_M[(long)Bv * Hv * EEv];   // 32 MB : M_{b,h}
__device__ float g_N[(long)Bv * EEv];        // 4 MB  : N_b
__device__ float g_ksum[Bv * Ev];
__device__ float g_vsum[Bv * Ev];
__device__ float g_a[Bv * Hv * Ev];          // Wk_h @ ksum_b
__device__ float g_w[Bv * Hv * Ev];          // Wv_h @ vsum_b
__device__ float g_r[Bv * HEv];              // bq_h^T M_{b,h}, concatenated over h
__device__ float g_c[Bv * Ev];               // per-batch output bias row

// ---------------- small kernels ----------------

// ksum[b,e] = sum_s k[b,s,e]; vsum likewise. grid=B, block=512
__global__ void colsum_kernel(const float* __restrict__ k, const float* __restrict__ v,
                              float* __restrict__ ksum, float* __restrict__ vsum) {
    int b = blockIdx.x;
    int e = threadIdx.x;
    const float* kb = k + (long)b * Sv * Ev;
    const float* vb = v + (long)b * Sv * Ev;
    float sk = 0.f, sv = 0.f;
    for (int s = 0; s < Sv; s++) {
        sk += kb[(long)s * Ev + e];
        sv += vb[(long)s * Ev + e];
    }
    ksum[b * Ev + e] = sk;
    vsum[b * Ev + e] = sv;
}

// out[z*E + o] = dot(W[h, o, :], x[b, :]) with z = b*H + h. One warp per row.
// total rows = B*H*E = 16384; launch 2048 blocks x 256 threads (8 warps)
__global__ void rowdot_kernel(const float* __restrict__ W, const float* __restrict__ x,
                              float* __restrict__ out) {
    int gw = (blockIdx.x * blockDim.x + threadIdx.x) >> 5;
    int lane = threadIdx.x & 31;
    int o = gw & (Ev - 1);
    int z = gw >> 9;           // E = 512 = 2^9
    int h = z & (Hv - 1);
    int b = z >> 3;            // H = 8
    const float* wr = W + (long)(h * Ev + o) * Ev;
    const float* xr = x + b * Ev;
    float s = 0.f;
    for (int e = lane; e < Ev; e += 32) s += wr[e] * xr[e];
    #pragma unroll
    for (int off = 16; off > 0; off >>= 1) s += __shfl_xor_sync(0xFFFFFFFFu, s, off);
    if (lane == 0) out[gw] = s;
}

// M[z,o1,o2] = (M + a[z,o1]*bv[h,o2] + bk[h,o1]*w[z,o2] + S*bk[h,o1]*bv[h,o2]) / E
__global__ void m_epilogue_kernel(float* __restrict__ M, const float* __restrict__ a,
                                  const float* __restrict__ w, const float* __restrict__ bk,
                                  const float* __restrict__ bv) {
    long idx = (long)blockIdx.x * blockDim.x + threadIdx.x;  // < B*H*E*E
    int o2 = (int)(idx & (Ev - 1));
    int o1 = (int)((idx >> 9) & (Ev - 1));
    int z = (int)(idx >> 18);
    int h = z & (Hv - 1);
    float bk1 = bk[h * Ev + o1];
    float bv2 = bv[h * Ev + o2];
    float t = M[idx] + a[z * Ev + o1] * bv2 + bk1 * w[z * Ev + o2] + (float)Sv * bk1 * bv2;
    M[idx] = t * (1.0f / (float)Ev);
}

// r[b*HE + h*E + o2] = sum_o bq[h,o] * M[(b*H+h)*EE + o*E + o2]
// 16384 outputs -> 64 blocks x 256
__global__ void rcat_kernel(const float* __restrict__ bq, const float* __restrict__ M,
                            float* __restrict__ r) {
    int idx = blockIdx.x * blockDim.x + threadIdx.x;  // z*E + o2, z = b*H + h
    int o2 = idx & (Ev - 1);
    int z = idx >> 9;
    int h = z & (Hv - 1);
    const float* Mz = M + (long)z * EEv;
    const float* bqh = bq + h * Ev;
    float s = 0.f;
    for (int o = 0; o < Ev; o++) s += bqh[o] * Mz[(long)o * Ev + o2];
    r[idx] = s;   // idx = b*4096 + h*512 + o2
}

// c[b*E + e2] = bo[e2] + sum_f r[b,f] * Wo[e2, f]. One warp per output (2048 warps).
__global__ void cvec_kernel(const float* __restrict__ r, const float* __restrict__ Wo,
                            const float* __restrict__ bo, float* __restrict__ c) {
    int gw = (blockIdx.x * blockDim.x + threadIdx.x) >> 5;  // b*E + e2
    int lane = threadIdx.x & 31;
    int e2 = gw & (Ev - 1);
    int b = gw >> 9;
    const float* rr = r + b * HEv;
    const float* wr = Wo + (long)e2 * HEv;
    float s = 0.f;
    for (int f = lane; f < HEv; f += 32) s += rr[f] * wr[f];
    #pragma unroll
    for (int off = 16; off > 0; off >>= 1) s += __shfl_xor_sync(0xFFFFFFFFu, s, off);
    if (lane == 0) c[gw] = s + bo[e2];
}

// ---------------- generic tiled SGEMM ----------------
// C(m,n) = sum_k A(m,k) B(k,n)  [+ bias(n) per batch]
//   TA: A physically [K, M] row-major (access phys[k*lda + m]); else [M, K]
//   TB: B physically [N, K] row-major (access phys[n*ldb + k]); else [K, N]
// Batch z = blockIdx.z; offsets = (z%zmod)*S1 + (z/zmod)*S2 per operand.
// All of M, N divisible by 64 and K by 16 (guaranteed by problem shapes).
#define BM 64
#define BN 64
#define BK 16

template <bool TA, bool TB, bool BIAS>
__global__ void gemm_kernel(const float* __restrict__ A, const float* __restrict__ B,
                            float* __restrict__ C, const float* __restrict__ bias,
                            int K, int lda, int ldb, int ldc,
                            int zmod, long aS1, long aS2, long bS1, long bS2,
                            long cS1, long cS2, long biasStride) {
    int z = blockIdx.z;
    int zm = z % zmod, zd = z / zmod;
    A += zm * aS1 + zd * aS2;
    B += zm * bS1 + zd * bS2;
    C += zm * cS1 + zd * cS2;

    __shared__ float As[BK][BM];
    __shared__ float Bs[BK][BN];

    int tid = threadIdx.x;          // 256 threads
    int tx = tid & 15;              // n-direction
    int ty = tid >> 4;              // m-direction
    int m0 = blockIdx.y * BM;
    int n0 = blockIdx.x * BN;

    float acc[4][4] = {};

    for (int k0 = 0; k0 < K; k0 += BK) {
        // ---- load A tile into As[kk][m] ----
        if (!TA) {
            int m = tid >> 2;             // 0..63
            int kg = (tid & 3) << 2;      // 0,4,8,12
            float4 av = *reinterpret_cast<const float4*>(&A[(long)(m0 + m) * lda + k0 + kg]);
            As[kg + 0][m] = av.x; As[kg + 1][m] = av.y;
            As[kg + 2][m] = av.z; As[kg + 3][m] = av.w;
        } else {
            int kk = tid >> 4;            // 0..15
            int mg = (tid & 15) << 2;     // 0..60
            *reinterpret_cast<float4*>(&As[kk][mg]) =
                *reinterpret_cast<const float4*>(&A[(long)(k0 + kk) * lda + m0 + mg]);
        }
        // ---- load B tile into Bs[kk][n] ----
        if (!TB) {
            int kk = tid >> 4;
            int ng = (tid & 15) << 2;
            *reinterpret_cast<float4*>(&Bs[kk][ng]) =
                *reinterpret_cast<const float4*>(&B[(long)(k0 + kk) * ldb + n0 + ng]);
        } else {
            int n = tid >> 2;
            int kg = (tid & 3) << 2;
            float4 bvv = *reinterpret_cast<const float4*>(&B[(long)(n0 + n) * ldb + k0 + kg]);
            Bs[kg + 0][n] = bvv.x; Bs[kg + 1][n] = bvv.y;
            Bs[kg + 2][n] = bvv.z; Bs[kg + 3][n] = bvv.w;
        }
        __syncthreads();

        #pragma unroll
        for (int kk = 0; kk < BK; kk++) {
            float a[4], b[4];
            *reinterpret_cast<float4*>(a) = *reinterpret_cast<const float4*>(&As[kk][ty << 2]);
            *reinterpret_cast<float4*>(b) = *reinterpret_cast<const float4*>(&Bs[kk][tx << 2]);
            #pragma unroll
            for (int i = 0; i < 4; i++)
                #pragma unroll
                for (int j = 0; j < 4; j++)
                    acc[i][j] += a[i] * b[j];
        }
        __syncthreads();
    }

    float bvec[4] = {0.f, 0.f, 0.f, 0.f};
    if (BIAS) {
        const float* bp = bias + zd * biasStride;
        #pragma unroll
        for (int j = 0; j < 4; j++) bvec[j] = bp[n0 + (tx << 2) + j];
    }

    #pragma unroll
    for (int i = 0; i < 4; i++) {
        float4 o;
        o.x = acc[i][0] + bvec[0];
        o.y = acc[i][1] + bvec[1];
        o.z = acc[i][2] + bvec[2];
        o.w = acc[i][3] + bvec[3];
        *reinterpret_cast<float4*>(&C[(long)(m0 + (ty << 2) + i) * ldc + n0 + (tx << 2)]) = o;
    }
}

// ---------------- launcher ----------------
extern "C" void kernel_launch(void* const* d_in, const int* in_sizes, int n_in,
                              void* d_out, int out_size) {
    const float* q  = (const float*)d_in[0];
    const float* k  = (const float*)d_in[1];
    const float* v  = (const float*)d_in[2];
    const float* Wq = (const float*)d_in[3];
    const float* bq = (const float*)d_in[4];
    const float* Wk = (const float*)d_in[5];
    const float* bk = (const float*)d_in[6];
    const float* Wv = (const float*)d_in[7];
    const float* bv = (const float*)d_in[8];
    const float* Wo = (const float*)d_in[9];
    const float* bo = (const float*)d_in[10];
    float* out = (float*)d_out;

    float *G, *T, *M, *N, *ksum, *vsum, *a, *w, *r, *c;
    cudaGetSymbolAddress((void**)&G, g_G);
    cudaGetSymbolAddress((void**)&T, g_T);
    cudaGetSymbolAddress((void**)&M, g_M);
    cudaGetSymbolAddress((void**)&N, g_N);
    cudaGetSymbolAddress((void**)&ksum, g_ksum);
    cudaGetSymbolAddress((void**)&vsum, g_vsum);
    cudaGetSymbolAddress((void**)&a, g_a);
    cudaGetSymbolAddress((void**)&w, g_w);
    cudaGetSymbolAddress((void**)&r, g_r);
    cudaGetSymbolAddress((void**)&c, g_c);

    const long EE = EEv, HEE = (long)Hv * EEv, SE = (long)Sv * Ev, EHE = (long)Ev * HEv;

    // 1) column sums of k, v
    colsum_kernel<<<Bv, Ev>>>(k, v, ksum, vsum);

    // 2) a = Wk_h @ ksum_b ; w = Wv_h @ vsum_b   (B*H*E warps each)
    rowdot_kernel<<<2048, 256>>>(Wk, ksum, a);
    rowdot_kernel<<<2048, 256>>>(Wv, vsum, w);

    // 3) G_b = k_b^T v_b   [512,512,K=2048], batched over b
    gemm_kernel<true, false, false><<<dim3(8, 8, Bv), 256>>>(
        k, v, G, nullptr, Sv, Ev, Ev, Ev,
        1, 0, SE, 0, SE, 0, EE, 0);

    // 4) T1_{b,h} = Wk_h @ G_b   [512^3], batched over z=b*H+h
    gemm_kernel<false, false, false><<<dim3(8, 8, Bv * Hv), 256>>>(
        Wk, G, T, nullptr, Ev, Ev, Ev, Ev,
        Hv, EE, 0, 0, EE, EE, HEE, 0);

    // 5) M_{b,h} = T1 @ Wv_h^T
    gemm_kernel<false, true, false><<<dim3(8, 8, Bv * Hv), 256>>>(
        T, Wv, M, nullptr, Ev, Ev, Ev, Ev,
        Hv, EE, HEE, EE, 0, EE, HEE, 0);

    // 6) rank-1 corrections + 1/E scale on M
    m_epilogue_kernel<<<32768, 256>>>(M, a, w, bk, bv);

    // 7) bias row pieces: r = bq_h^T M_{b,h}, then c = r @ Wo^T + bo
    rcat_kernel<<<64, 256>>>(bq, M, r);
    cvec_kernel<<<256, 256>>>(r, Wo, bo, c);

    // 8) T3s[b][e][h*E+o2] = (Wq_h^T @ M_{b,h})(e,o2)   (reuse T)
    gemm_kernel<true, false, false><<<dim3(8, 8, Bv * Hv), 256>>>(
        Wq, M, T, nullptr, Ev, Ev, Ev, HEv,
        Hv, EE, 0, EE, HEE, (long)Ev, EHE, 0);

    // 9) N_b = T3s[b] @ Wo^T   [512,512,K=4096]
    gemm_kernel<false, true, false><<<dim3(8, 8, Bv), 256>>>(
        T, Wo, N, nullptr, HEv, HEv, HEv, Ev,
        1, 0, EHE, 0, 0, 0, EE, 0);

    // 10) out_b = q_b @ N_b + c_b   [2048,512,K=512]
    gemm_kernel<false, false, true><<<dim3(8, 32, Bv), 256>>>(
        q, N, out, c, Ev, Ev, Ev, Ev,
        1, 0, SE, 0, EE, 0, SE, (long)Ev);
}

// round 2
// speedup vs baseline: 1.0023x; 1.0023x over previous
#include <cuda_runtime.h>
#include <cuda_bf16.h>

// Problem constants
#define Bv 4
#define Sv 2048
#define Ev 512
#define Hv 8
#define HEv 4096            // H*E
#define EEv 262144          // E*E

// ---------------- scratch (static device globals; no allocation) ----------------
__device__ float g_G[(long)Bv * EEv];        // 4 MB  : G_b = k_b^T v_b
__device__ float g_T[(long)Bv * Hv * EEv];   // 32 MB : T1 then reused as T3s [B][E][H*E]
__device__ float g_M[(long)Bv * Hv * EEv];   // 32 MB : M_{b,h}
__device__ float g_N[(long)Bv * EEv];        // 4 MB  : N_b
__device__ float g_ksum[Bv * Ev];
__device__ float g_vsum[Bv * Ev];
__device__ float g_a[Bv * Hv * Ev];          // Wk_h @ ksum_b
__device__ float g_w[Bv * Hv * Ev];          // Wv_h @ vsum_b
__device__ float g_r[Bv * HEv];              // bq_h^T M_{b,h}, concatenated over h
__device__ float g_c[Bv * Ev];               // per-batch output bias row

// ---------------- small kernels ----------------

// ksum[b,e] = sum_s k[b,s,e]; vsum likewise. grid=B, block=512
__global__ void colsum_kernel(const float* __restrict__ k, const float* __restrict__ v,
                              float* __restrict__ ksum, float* __restrict__ vsum) {
    int b = blockIdx.x;
    int e = threadIdx.x;
    const float* kb = k + (long)b * Sv * Ev;
    const float* vb = v + (long)b * Sv * Ev;
    float sk = 0.f, sv = 0.f;
    for (int s = 0; s < Sv; s++) {
        sk += kb[(long)s * Ev + e];
        sv += vb[(long)s * Ev + e];
    }
    ksum[b * Ev + e] = sk;
    vsum[b * Ev + e] = sv;
}

// out[z*E + o] = dot(W[h, o, :], x[b, :]) with z = b*H + h. One warp per row.
// total rows = B*H*E = 16384; launch 2048 blocks x 256 threads (8 warps)
__global__ void rowdot_kernel(const float* __restrict__ W, const float* __restrict__ x,
                              float* __restrict__ out) {
    int gw = (blockIdx.x * blockDim.x + threadIdx.x) >> 5;
    int lane = threadIdx.x & 31;
    int o = gw & (Ev - 1);
    int z = gw >> 9;           // E = 512 = 2^9
    int h = z & (Hv - 1);
    int b = z >> 3;            // H = 8
    const float* wr = W + (long)(h * Ev + o) * Ev;
    const float* xr = x + b * Ev;
    float s = 0.f;
    for (int e = lane; e < Ev; e += 32) s += wr[e] * xr[e];
    #pragma unroll
    for (int off = 16; off > 0; off >>= 1) s += __shfl_xor_sync(0xFFFFFFFFu, s, off);
    if (lane == 0) out[gw] = s;
}

// M[z,o1,o2] = (M + a[z,o1]*bv[h,o2] + bk[h,o1]*w[z,o2] + S*bk[h,o1]*bv[h,o2]) / E
__global__ void m_epilogue_kernel(float* __restrict__ M, const float* __restrict__ a,
                                  const float* __restrict__ w, const float* __restrict__ bk,
                                  const float* __restrict__ bv) {
    long idx = (long)blockIdx.x * blockDim.x + threadIdx.x;  // < B*H*E*E
    int o2 = (int)(idx & (Ev - 1));
    int o1 = (int)((idx >> 9) & (Ev - 1));
    int z = (int)(idx >> 18);
    int h = z & (Hv - 1);
    float bk1 = bk[h * Ev + o1];
    float bv2 = bv[h * Ev + o2];
    float t = M[idx] + a[z * Ev + o1] * bv2 + bk1 * w[z * Ev + o2] + (float)Sv * bk1 * bv2;
    M[idx] = t * (1.0f / (float)Ev);
}

// r[b*HE + h*E + o2] = sum_o bq[h,o] * M[(b*H+h)*EE + o*E + o2]
// 16384 outputs -> 64 blocks x 256
__global__ void rcat_kernel(const float* __restrict__ bq, const float* __restrict__ M,
                            float* __restrict__ r) {
    int idx = blockIdx.x * blockDim.x + threadIdx.x;  // z*E + o2, z = b*H + h
    int o2 = idx & (Ev - 1);
    int z = idx >> 9;
    int h = z & (Hv - 1);
    const float* Mz = M + (long)z * EEv;
    const float* bqh = bq + h * Ev;
    float s = 0.f;
    for (int o = 0; o < Ev; o++) s += bqh[o] * Mz[(long)o * Ev + o2];
    r[idx] = s;   // idx = b*4096 + h*512 + o2
}

// c[b*E + e2] = bo[e2] + sum_f r[b,f] * Wo[e2, f]. One warp per output (2048 warps).
__global__ void cvec_kernel(const float* __restrict__ r, const float* __restrict__ Wo,
                            const float* __restrict__ bo, float* __restrict__ c) {
    int gw = (blockIdx.x * blockDim.x + threadIdx.x) >> 5;  // b*E + e2
    int lane = threadIdx.x & 31;
    int e2 = gw & (Ev - 1);
    int b = gw >> 9;
    const float* rr = r + b * HEv;
    const float* wr = Wo + (long)e2 * HEv;
    float s = 0.f;
    for (int f = lane; f < HEv; f += 32) s += rr[f] * wr[f];
    #pragma unroll
    for (int off = 16; off > 0; off >>= 1) s += __shfl_xor_sync(0xFFFFFFFFu, s, off);
    if (lane == 0) c[gw] = s + bo[e2];
}

// ---------------- generic tiled SGEMM ----------------
// C(m,n) = sum_k A(m,k) B(k,n)  [+ bias(n) per batch]
//   TA: A physically [K, M] row-major (access phys[k*lda + m]); else [M, K]
//   TB: B physically [N, K] row-major (access phys[n*ldb + k]); else [K, N]
// Batch z = blockIdx.z; offsets = (z%zmod)*S1 + (z/zmod)*S2 per operand.
// All of M, N divisible by 64 and K by 16 (guaranteed by problem shapes).
#define BM 64
#define BN 64
#define BK 16

template <bool TA, bool TB, bool BIAS>
__global__ void gemm_kernel(const float* __restrict__ A, const float* __restrict__ B,
                            float* __restrict__ C, const float* __restrict__ bias,
                            int K, int lda, int ldb, int ldc,
                            int zmod, long aS1, long aS2, long bS1, long bS2,
                            long cS1, long cS2, long biasStride) {
    int z = blockIdx.z;
    int zm = z % zmod, zd = z / zmod;
    A += zm * aS1 + zd * aS2;
    B += zm * bS1 + zd * bS2;
    C += zm * cS1 + zd * cS2;

    __shared__ float As[BK][BM];
    __shared__ float Bs[BK][BN];

    int tid = threadIdx.x;          // 256 threads
    int tx = tid & 15;              // n-direction
    int ty = tid >> 4;              // m-direction
    int m0 = blockIdx.y * BM;
    int n0 = blockIdx.x * BN;

    float acc[4][4] = {};

    for (int k0 = 0; k0 < K; k0 += BK) {
        // ---- load A tile into As[kk][m] ----
        if (!TA) {
            int m = tid >> 2;             // 0..63
            int kg = (tid & 3) << 2;      // 0,4,8,12
            float4 av = *reinterpret_cast<const float4*>(&A[(long)(m0 + m) * lda + k0 + kg]);
            As[kg + 0][m] = av.x; As[kg + 1][m] = av.y;
            As[kg + 2][m] = av.z; As[kg + 3][m] = av.w;
        } else {
            int kk = tid >> 4;            // 0..15
            int mg = (tid & 15) << 2;     // 0..60
            *reinterpret_cast<float4*>(&As[kk][mg]) =
                *reinterpret_cast<const float4*>(&A[(long)(k0 + kk) * lda + m0 + mg]);
        }
        // ---- load B tile into Bs[kk][n] ----
        if (!TB) {
            int kk = tid >> 4;
            int ng = (tid & 15) << 2;
            *reinterpret_cast<float4*>(&Bs[kk][ng]) =
                *reinterpret_cast<const float4*>(&B[(long)(k0 + kk) * ldb + n0 + ng]);
        } else {
            int n = tid >> 2;
            int kg = (tid & 3) << 2;
            float4 bvv = *reinterpret_cast<const float4*>(&B[(long)(n0 + n) * ldb + k0 + kg]);
            Bs[kg + 0][n] = bvv.x; Bs[kg + 1][n] = bvv.y;
            Bs[kg + 2][n] = bvv.z; Bs[kg + 3][n] = bvv.w;
        }
        __syncthreads();

        #pragma unroll
        for (int kk = 0; kk < BK; kk++) {
            float a[4], b[4];
            *reinterpret_cast<float4*>(a) = *reinterpret_cast<const float4*>(&As[kk][ty << 2]);
            *reinterpret_cast<float4*>(b) = *reinterpret_cast<const float4*>(&Bs[kk][tx << 2]);
            #pragma unroll
            for (int i = 0; i < 4; i++)
                #pragma unroll
                for (int j = 0; j < 4; j++)
                    acc[i][j] += a[i] * b[j];
        }
        __syncthreads();
    }

    float bvec[4] = {0.f, 0.f, 0.f, 0.f};
    if (BIAS) {
        const float* bp = bias + zd * biasStride;
        #pragma unroll
        for (int j = 0; j < 4; j++) bvec[j] = bp[n0 + (tx << 2) + j];
    }

    #pragma unroll
    for (int i = 0; i < 4; i++) {
        float4 o;
        o.x = acc[i][0] + bvec[0];
        o.y = acc[i][1] + bvec[1];
        o.z = acc[i][2] + bvec[2];
        o.w = acc[i][3] + bvec[3];
        *reinterpret_cast<float4*>(&C[(long)(m0 + (ty << 2) + i) * ldc + n0 + (tx << 2)]) = o;
    }
}

// ---------------- launcher ----------------
extern "C" void kernel_launch(void* const* d_in, const int* in_sizes, int n_in,
                              void* d_out, int out_size) {
    const float* q  = (const float*)d_in[0];
    const float* k  = (const float*)d_in[1];
    const float* v  = (const float*)d_in[2];
    const float* Wq = (const float*)d_in[3];
    const float* bq = (const float*)d_in[4];
    const float* Wk = (const float*)d_in[5];
    const float* bk = (const float*)d_in[6];
    const float* Wv = (const float*)d_in[7];
    const float* bv = (const float*)d_in[8];
    const float* Wo = (const float*)d_in[9];
    const float* bo = (const float*)d_in[10];
    float* out = (float*)d_out;

    float *G, *T, *M, *N, *ksum, *vsum, *a, *w, *r, *c;
    cudaGetSymbolAddress((void**)&G, g_G);
    cudaGetSymbolAddress((void**)&T, g_T);
    cudaGetSymbolAddress((void**)&M, g_M);
    cudaGetSymbolAddress((void**)&N, g_N);
    cudaGetSymbolAddress((void**)&ksum, g_ksum);
    cudaGetSymbolAddress((void**)&vsum, g_vsum);
    cudaGetSymbolAddress((void**)&a, g_a);
    cudaGetSymbolAddress((void**)&w, g_w);
    cudaGetSymbolAddress((void**)&r, g_r);
    cudaGetSymbolAddress((void**)&c, g_c);

    const long EE = EEv, HEE = (long)Hv * EEv, SE = (long)Sv * Ev, EHE = (long)Ev * HEv;

    // 1) column sums of k, v
    colsum_kernel<<<Bv, Ev>>>(k, v, ksum, vsum);

    // 2) a = Wk_h @ ksum_b ; w = Wv_h @ vsum_b   (B*H*E warps each)
    rowdot_kernel<<<2048, 256>>>(Wk, ksum, a);
    rowdot_kernel<<<2048, 256>>>(Wv, vsum, w);

    // 3) G_b = k_b^T v_b   [512,512,K=2048], batched over b
    gemm_kernel<true, false, false><<<dim3(8, 8, Bv), 256>>>(
        k, v, G, nullptr, Sv, Ev, Ev, Ev,
        1, 0, SE, 0, SE, 0, EE, 0);

    // 4) T1_{b,h} = Wk_h @ G_b   [512^3], batched over z=b*H+h
    gemm_kernel<false, false, false><<<dim3(8, 8, Bv * Hv), 256>>>(
        Wk, G, T, nullptr, Ev, Ev, Ev, Ev,
        Hv, EE, 0, 0, EE, EE, HEE, 0);

    // 5) M_{b,h} = T1 @ Wv_h^T
    gemm_kernel<false, true, false><<<dim3(8, 8, Bv * Hv), 256>>>(
        T, Wv, M, nullptr, Ev, Ev, Ev, Ev,
        Hv, EE, HEE, EE, 0, EE, HEE, 0);

    // 6) rank-1 corrections + 1/E scale on M
    m_epilogue_kernel<<<32768, 256>>>(M, a, w, bk, bv);

    // 7) bias row pieces: r = bq_h^T M_{b,h}, then c = r @ Wo^T + bo
    rcat_kernel<<<64, 256>>>(bq, M, r);
    cvec_kernel<<<256, 256>>>(r, Wo, bo, c);

    // 8) T3s[b][e][h*E+o2] = (Wq_h^T @ M_{b,h})(e,o2)   (reuse T)
    gemm_kernel<true, false, false><<<dim3(8, 8, Bv * Hv), 256>>>(
        Wq, M, T, nullptr, Ev, Ev, Ev, HEv,
        Hv, EE, 0, EE, HEE, (long)Ev, EHE, 0);

    // 9) N_b = T3s[b] @ Wo^T   [512,512,K=4096]
    gemm_kernel<false, true, false><<<dim3(8, 8, Bv), 256>>>(
        T, Wo, N, nullptr, HEv, HEv, HEv, Ev,
        1, 0, EHE, 0, 0, 0, EE, 0);

    // 10) out_b = q_b @ N_b + c_b   [2048,512,K=512]
    gemm_kernel<false, false, true><<<dim3(8, 32, Bv), 256>>>(
        q, N, out, c, Ev, Ev, Ev, Ev,
        1, 0, SE, 0, EE, 0, SE, (long)Ev);
}

// round 4
// speedup vs baseline: 1.7259x; 1.7219x over previous
#include <cuda_runtime.h>
#include <cuda_bf16.h>
#include <cstdint>

#define Bv 4
#define Sv 2048
#define Ev 512
#define Hv 8
#define HEv 4096
#define EEv 262144

// fp32 intermediates
__device__ float g_G[(long)Bv * EEv];        // GT
__device__ float g_T[(long)Bv * Hv * EEv];   // T1 then T3
__device__ float g_M[(long)Bv * Hv * EEv];   // MT
__device__ float g_N[(long)Bv * EEv];        // NT
__device__ float g_ksum[Bv * Ev], g_vsum[Bv * Ev];
__device__ float g_a[Bv * Hv * Ev], g_w[Bv * Hv * Ev];
__device__ float g_r[Bv * HEv], g_c[Bv * Ev];

// bf16 hi|lo buffers (lo at +half)
__device__ __nv_bfloat16 c_kT [2L * Bv * Ev * Sv];
__device__ __nv_bfloat16 c_vT [2L * Bv * Ev * Sv];
__device__ __nv_bfloat16 c_Wk [2L * Hv * EEv];
__device__ __nv_bfloat16 c_Wv [2L * Hv * EEv];
__device__ __nv_bfloat16 c_WqT[2L * Hv * EEv];
__device__ __nv_bfloat16 c_Wo [2L * Ev * HEv];
__device__ __nv_bfloat16 c_GT [2L * Bv * EEv];
__device__ __nv_bfloat16 c_T1 [2L * Bv * Hv * EEv];
__device__ __nv_bfloat16 c_MT [2L * Bv * Hv * EEv];
__device__ __nv_bfloat16 c_T3 [2L * Bv * Ev * HEv];
__device__ __nv_bfloat16 c_q  [2L * Bv * Sv * Ev];
__device__ __nv_bfloat16 c_NT [2L * Bv * EEv];

__device__ __forceinline__ uint32_t smem_u32(const void* p) {
    uint32_t a;
    asm("{ .reg .u64 t; cvta.to.shared.u64 t, %1; cvt.u32.u64 %0, t; }" : "=r"(a) : "l"(p));
    return a;
}
__device__ __forceinline__ void cpa16(uint32_t dst, const void* src) {
    asm volatile("cp.async.cg.shared.global [%0], [%1], 16;" :: "r"(dst), "l"(src));
}
__device__ __forceinline__ void ldsm4(uint32_t* r, uint32_t addr) {
    asm volatile("ldmatrix.sync.aligned.m8n8.x4.shared.b16 {%0,%1,%2,%3}, [%4];"
        : "=r"(r[0]), "=r"(r[1]), "=r"(r[2]), "=r"(r[3]) : "r"(addr));
}
__device__ __forceinline__ void mma_bf16(float* d, const uint32_t* a, const uint32_t* b) {
    asm volatile("mma.sync.aligned.m16n8k16.row.col.f32.bf16.bf16.f32 "
        "{%0,%1,%2,%3}, {%4,%5,%6,%7}, {%8,%9}, {%0,%1,%2,%3};"
        : "+f"(d[0]), "+f"(d[1]), "+f"(d[2]), "+f"(d[3])
        : "r"(a[0]), "r"(a[1]), "r"(a[2]), "r"(a[3]), "r"(b[0]), "r"(b[1]));
}

#define SMEM_DYN 65536   // 2 stages x (A 16KB + B 16KB)

// C(m,n) = sum_k A(m,k)*B(n,k); A,B bf16 [rows][K] row-major, K % 64 == 0.
// K tripled via hi/lo phases: [Ah*Bh, Ah*Bl, Al*Bh]. Tile 128x128, chunk 64.
template <bool BIAS>
__global__ void __launch_bounds__(256, 1)
tgemm(const __nv_bfloat16* __restrict__ Ahi, const __nv_bfloat16* __restrict__ Alo,
      const __nv_bfloat16* __restrict__ Bhi, const __nv_bfloat16* __restrict__ Blo,
      float* __restrict__ C, const float* __restrict__ bias,
      int K, int ldc, int zmod,
      long aS1, long aS2, long bS1, long bS2, long cS1, long cS2, long biasStride)
{
    extern __shared__ __align__(128) char dsm[];
    uint32_t sbase = smem_u32(dsm);

    int tid = threadIdx.x, wid = tid >> 5, lane = tid & 31;
    int z = blockIdx.z, zm = z % zmod, zd = z / zmod;
    Ahi += zm * aS1 + zd * aS2;  Alo += zm * aS1 + zd * aS2;
    Bhi += zm * bS1 + zd * bS2;  Blo += zm * bS1 + zd * bS2;
    C   += zm * cS1 + zd * cS2;
    int m0 = blockIdx.y * 128, n0 = blockIdx.x * 128;

    const int CPP = K >> 6;        // chunks per phase
    const int NC = 3 * CPP;

    int srow = tid >> 3, scs = tid & 7;          // cp.async: this thread's (row%?, 16B col)
    // each thread does 8 transfers: 4 rows of A (row = srow + 32*i), 4 of B

    auto issue = [&](int c) {
        int phase = c / CPP;
        int kpos = (c - phase * CPP) << 6;
        const __nv_bfloat16* pa = (phase < 2) ? Ahi : Alo;
        const __nv_bfloat16* pb = (phase == 1) ? Blo : Bhi;
        uint32_t sb = sbase + (uint32_t)((c & 1) << 15);
        #pragma unroll
        for (int t = 0; t < 8; t++) {
            int isB = t >> 2;
            int row = srow + ((t & 3) << 5);
            const __nv_bfloat16* src = (isB ? pb : pa) +
                (long)((isB ? n0 : m0) + row) * K + kpos + (scs << 3);
            uint32_t bo = (uint32_t)((row << 7) + (scs << 4));
            bo ^= (uint32_t)((row & 7) << 4);
            cpa16(sb + (uint32_t)(isB << 14) + bo, src);
        }
        asm volatile("cp.async.commit_group;" ::: "memory");
    };

    issue(0);
    issue(1);

    float acc[2][8][4] = {};
    int moff = (wid & 3) << 5;     // 0,32,64,96
    int noff = (wid >> 2) << 6;    // 0,64

    for (int c = 0; c < NC; c++) {
        if (c + 1 < NC) asm volatile("cp.async.wait_group 1;" ::: "memory");
        else            asm volatile("cp.async.wait_group 0;" ::: "memory");
        __syncthreads();
        uint32_t sb = sbase + (uint32_t)((c & 1) << 15);

        #pragma unroll
        for (int ks = 0; ks < 4; ks++) {
            uint32_t afr[2][4];
            #pragma unroll
            for (int i = 0; i < 2; i++) {
                int row = moff + (i << 4) + (lane & 15);
                int colb = (ks << 5) + ((lane >> 4) << 4);
                uint32_t bo = (uint32_t)((row << 7) + colb) ^ (uint32_t)((row & 7) << 4);
                ldsm4(afr[i], sb + bo);
            }
            uint32_t bfr[8][2];
            #pragma unroll
            for (int j2 = 0; j2 < 4; j2++) {
                int row = noff + (j2 << 4) + ((lane >> 4) << 3) + (lane & 7);
                int colb = (ks << 5) + (((lane >> 3) & 1) << 4);
                uint32_t bo = (uint32_t)((row << 7) + colb) ^ (uint32_t)((row & 7) << 4);
                uint32_t r[4];
                ldsm4(r, sb + 16384u + bo);
                bfr[2 * j2][0] = r[0]; bfr[2 * j2][1] = r[1];
                bfr[2 * j2 + 1][0] = r[2]; bfr[2 * j2 + 1][1] = r[3];
            }
            #pragma unroll
            for (int i = 0; i < 2; i++)
                #pragma unroll
                for (int j = 0; j < 8; j++)
                    mma_bf16(acc[i][j], afr[i], bfr[j]);
        }
        __syncthreads();
        if (c + 2 < NC) issue(c + 2);
    }

    // epilogue: lane l holds rows g, g+8 (g = l/4), col pair 2*(l%4) per 16x8 tile
    int g = lane >> 2, t4 = lane & 3;
    const float* bp = BIAS ? (bias + zd * biasStride) : nullptr;
    #pragma unroll
    for (int i = 0; i < 2; i++) {
        int row0 = m0 + moff + (i << 4) + g;
        #pragma unroll
        for (int j = 0; j < 8; j++) {
            int col = n0 + noff + (j << 3) + (t4 << 1);
            float bx = 0.f, by = 0.f;
            if (BIAS) { float2 bb = *reinterpret_cast<const float2*>(bp + col); bx = bb.x; by = bb.y; }
            float2 o0 = make_float2(acc[i][j][0] + bx, acc[i][j][1] + by);
            float2 o1 = make_float2(acc[i][j][2] + bx, acc[i][j][3] + by);
            *reinterpret_cast<float2*>(&C[(long)row0 * ldc + col]) = o0;
            *reinterpret_cast<float2*>(&C[(long)(row0 + 8) * ldc + col]) = o1;
        }
    }
}

// elementwise fp32 -> bf16 hi/lo (count % 1024 == 0)
__global__ void conv_split(const float* __restrict__ src, __nv_bfloat16* __restrict__ hi,
                           __nv_bfloat16* __restrict__ lo) {
    long i = ((long)blockIdx.x * blockDim.x + threadIdx.x) * 4;
    float4 x = *reinterpret_cast<const float4*>(src + i);
    __nv_bfloat16 h0 = __float2bfloat16(x.x), h1 = __float2bfloat16(x.y);
    __nv_bfloat16 h2 = __float2bfloat16(x.z), h3 = __float2bfloat16(x.w);
    __nv_bfloat16 l0 = __float2bfloat16(x.x - __bfloat162float(h0));
    __nv_bfloat16 l1 = __float2bfloat16(x.y - __bfloat162float(h1));
    __nv_bfloat16 l2 = __float2bfloat16(x.z - __bfloat162float(h2));
    __nv_bfloat16 l3 = __float2bfloat16(x.w - __bfloat162float(h3));
    uint2 hp, lp;
    hp.x = (uint32_t)__bfloat16_as_ushort(h0) | ((uint32_t)__bfloat16_as_ushort(h1) << 16);
    hp.y = (uint32_t)__bfloat16_as_ushort(h2) | ((uint32_t)__bfloat16_as_ushort(h3) << 16);
    lp.x = (uint32_t)__bfloat16_as_ushort(l0) | ((uint32_t)__bfloat16_as_ushort(l1) << 16);
    lp.y = (uint32_t)__bfloat16_as_ushort(l2) | ((uint32_t)__bfloat16_as_ushort(l3) << 16);
    *reinterpret_cast<uint2*>(hi + i) = hp;
    *reinterpret_cast<uint2*>(lo + i) = lp;
}

// dst[r][k] = src[k][r], split. block (32,8); grid (srcRows/32, dstRows/32, Z)
__global__ void conv_tsplit(const float* __restrict__ src, __nv_bfloat16* __restrict__ hi,
                            __nv_bfloat16* __restrict__ lo,
                            int srcLd, long srcZ, int dstLd, long dstZ) {
    __shared__ float tile[32][33];
    int zz = blockIdx.z;
    src += (long)zz * srcZ;
    long dz = (long)zz * dstZ;
    int k0 = blockIdx.x * 32, r0 = blockIdx.y * 32;
    int tx = threadIdx.x, ty = threadIdx.y;
    #pragma unroll
    for (int i = 0; i < 4; i++)
        tile[ty + 8 * i][tx] = src[(long)(k0 + ty + 8 * i) * srcLd + r0 + tx];
    __syncthreads();
    #pragma unroll
    for (int i = 0; i < 4; i++) {
        int r = r0 + ty + 8 * i, kk = k0 + tx;
        float x = tile[tx][ty + 8 * i];
        __nv_bfloat16 h = __float2bfloat16(x);
        hi[dz + (long)r * dstLd + kk] = h;
        lo[dz + (long)r * dstLd + kk] = __float2bfloat16(x - __bfloat162float(h));
    }
}

__global__ void colsum_kernel(const float* __restrict__ k, const float* __restrict__ v,
                              float* __restrict__ ks, float* __restrict__ vs) {
    int b = blockIdx.x, e = threadIdx.x;
    const float* kb = k + (long)b * Sv * Ev;
    const float* vb = v + (long)b * Sv * Ev;
    float sk = 0.f, sv = 0.f;
    for (int s = 0; s < Sv; s++) { sk += kb[(long)s * Ev + e]; sv += vb[(long)s * Ev + e]; }
    ks[b * Ev + e] = sk; vs[b * Ev + e] = sv;
}
__global__ void rowdot_kernel(const float* __restrict__ W, const float* __restrict__ x,
                              float* __restrict__ out) {
    int gw = (blockIdx.x * blockDim.x + threadIdx.x) >> 5, lane = threadIdx.x & 31;
    int o = gw & (Ev - 1), zz = gw >> 9, h = zz & (Hv - 1), b = zz >> 3;
    const float* wr = W + (long)(h * Ev + o) * Ev;
    const float* xr = x + b * Ev;
    float s = 0.f;
    for (int e = lane; e < Ev; e += 32) s += wr[e] * xr[e];
    #pragma unroll
    for (int off = 16; off > 0; off >>= 1) s += __shfl_xor_sync(0xFFFFFFFFu, s, off);
    if (lane == 0) out[gw] = s;
}
// MT layout [z][o2][o1]
__global__ void m_epilogue_kernel(float* __restrict__ MT, const float* __restrict__ a,
                                  const float* __restrict__ w, const float* __restrict__ bk,
                                  const float* __restrict__ bv) {
    long idx = (long)blockIdx.x * blockDim.x + threadIdx.x;
    int o1 = (int)(idx & (Ev - 1));
    int o2 = (int)((idx >> 9) & (Ev - 1));
    int zz = (int)(idx >> 18);
    int h = zz & (Hv - 1);
    float bk1 = bk[h * Ev + o1], bv2 = bv[h * Ev + o2];
    float t = MT[idx] + a[zz * Ev + o1] * bv2 + bk1 * w[zz * Ev + o2] + (float)Sv * bk1 * bv2;
    MT[idx] = t * (1.0f / (float)Ev);
}
// r[z*E+o2] = sum_o bq[h,o]*MT[z][o2][o]  (one warp per output)
__global__ void rcat_kernel(const float* __restrict__ bq, const float* __restrict__ MT,
                            float* __restrict__ r) {
    int gw = (blockIdx.x * blockDim.x + threadIdx.x) >> 5, lane = threadIdx.x & 31;
    int o2 = gw & (Ev - 1), zz = gw >> 9, h = zz & (Hv - 1);
    const float* Mr = MT + (long)zz * EEv + (long)o2 * Ev;
    const float* bqh = bq + h * Ev;
    float s = 0.f;
    for (int o = lane; o < Ev; o += 32) s += bqh[o] * Mr[o];
    #pragma unroll
    for (int off = 16; off > 0; off >>= 1) s += __shfl_xor_sync(0xFFFFFFFFu, s, off);
    if (lane == 0) r[gw] = s;
}
__global__ void cvec_kernel(const float* __restrict__ r, const float* __restrict__ Wo,
                            const float* __restrict__ bo, float* __restrict__ c) {
    int gw = (blockIdx.x * blockDim.x + threadIdx.x) >> 5, lane = threadIdx.x & 31;
    int e2 = gw & (Ev - 1), b = gw >> 9;
    const float* rr = r + b * HEv;
    const float* wr = Wo + (long)e2 * HEv;
    float s = 0.f;
    for (int f = lane; f < HEv; f += 32) s += rr[f] * wr[f];
    #pragma unroll
    for (int off = 16; off > 0; off >>= 1) s += __shfl_xor_sync(0xFFFFFFFFu, s, off);
    if (lane == 0) c[gw] = s + bo[e2];
}

extern "C" void kernel_launch(void* const* d_in, const int* in_sizes, int n_in,
                              void* d_out, int out_size) {
    const float* q  = (const float*)d_in[0];
    const float* k  = (const float*)d_in[1];
    const float* v  = (const float*)d_in[2];
    const float* Wq = (const float*)d_in[3];
    const float* bq = (const float*)d_in[4];
    const float* Wk = (const float*)d_in[5];
    const float* bk = (const float*)d_in[6];
    const float* Wv = (const float*)d_in[7];
    const float* bv = (const float*)d_in[8];
    const float* Wo = (const float*)d_in[9];
    const float* bo = (const float*)d_in[10];
    float* out = (float*)d_out;

    float *G, *T, *M, *N, *ksum, *vsum, *a, *w, *r, *c;
    cudaGetSymbolAddress((void**)&G, g_G);
    cudaGetSymbolAddress((void**)&T, g_T);
    cudaGetSymbolAddress((void**)&M, g_M);
    cudaGetSymbolAddress((void**)&N, g_N);
    cudaGetSymbolAddress((void**)&ksum, g_ksum);
    cudaGetSymbolAddress((void**)&vsum, g_vsum);
    cudaGetSymbolAddress((void**)&a, g_a);
    cudaGetSymbolAddress((void**)&w, g_w);
    cudaGetSymbolAddress((void**)&r, g_r);
    cudaGetSymbolAddress((void**)&c, g_c);

    __nv_bfloat16 *kT, *vT, *bWk, *bWv, *bWqT, *bWo, *bGT, *bT1, *bMT, *bT3, *bq16, *bNT;
    cudaGetSymbolAddress((void**)&kT, c_kT);
    cudaGetSymbolAddress((void**)&vT, c_vT);
    cudaGetSymbolAddress((void**)&bWk, c_Wk);
    cudaGetSymbolAddress((void**)&bWv, c_Wv);
    cudaGetSymbolAddress((void**)&bWqT, c_WqT);
    cudaGetSymbolAddress((void**)&bWo, c_Wo);
    cudaGetSymbolAddress((void**)&bGT, c_GT);
    cudaGetSymbolAddress((void**)&bT1, c_T1);
    cudaGetSymbolAddress((void**)&bMT, c_MT);
    cudaGetSymbolAddress((void**)&bT3, c_T3);
    cudaGetSymbolAddress((void**)&bq16, c_q);
    cudaGetSymbolAddress((void**)&bNT, c_NT);

    cudaFuncSetAttribute(tgemm<false>, cudaFuncAttributeMaxDynamicSharedMemorySize, SMEM_DYN);
    cudaFuncSetAttribute(tgemm<true>,  cudaFuncAttributeMaxDynamicSharedMemorySize, SMEM_DYN);

    const long ES = (long)Ev * Sv, EE = EEv, HEE = (long)Hv * EEv;
    const long SE = (long)Sv * Ev, EHE = (long)Ev * HEv;
    const long hKT = (long)Bv * ES, hW = (long)Hv * EEv, hWo = (long)Ev * HEv;
    const long hGT = (long)Bv * EEv, hT1 = (long)Bv * Hv * EEv, hT3 = (long)Bv * EHE;
    const long hq = (long)Bv * SE, hNT = (long)Bv * EEv;

    // fp32 prep
    colsum_kernel<<<Bv, Ev>>>(k, v, ksum, vsum);
    rowdot_kernel<<<2048, 256>>>(Wk, ksum, a);
    rowdot_kernel<<<2048, 256>>>(Wv, vsum, w);

    // conversions of inputs
    dim3 tb(32, 8);
    conv_tsplit<<<dim3(64, 16, Bv), tb>>>(k, kT, kT + hKT, Ev, SE, Sv, ES);
    conv_tsplit<<<dim3(64, 16, Bv), tb>>>(v, vT, vT + hKT, Ev, SE, Sv, ES);
    conv_tsplit<<<dim3(16, 16, Hv), tb>>>(Wq, bWqT, bWqT + hW, Ev, EE, Ev, EE);
    conv_split<<<2048, 256>>>(Wk, bWk, bWk + hW);
    conv_split<<<2048, 256>>>(Wv, bWv, bWv + hW);
    conv_split<<<2048, 256>>>(Wo, bWo, bWo + hWo);
    conv_split<<<4096, 256>>>(q, bq16, bq16 + hq);

    // 1) GT_b[e2][e1] = sum_s v[s][e2] k[s][e1]
    tgemm<false><<<dim3(4, 4, Bv), 256, SMEM_DYN>>>(
        vT, vT + hKT, kT, kT + hKT, G, nullptr, Sv, Ev,
        1, 0, ES, 0, ES, 0, EE, 0);
    conv_split<<<1024, 256>>>(G, bGT, bGT + hGT);

    // 2) T1_z[o1][e2] = sum_e Wk[o1][e] GT[e2][e]
    tgemm<false><<<dim3(4, 4, Bv * Hv), 256, SMEM_DYN>>>(
        bWk, bWk + hW, bGT, bGT + hGT, T, nullptr, Ev, Ev,
        Hv, EE, 0, 0, EE, EE, HEE, 0);
    conv_split<<<8192, 256>>>(T, bT1, bT1 + hT1);

    // 3) MT_z[o2][o1] = sum_e2 Wv[o2][e2] T1[o1][e2]
    tgemm<false><<<dim3(4, 4, Bv * Hv), 256, SMEM_DYN>>>(
        bWv, bWv + hW, bT1, bT1 + hT1, M, nullptr, Ev, Ev,
        Hv, EE, 0, EE, HEE, EE, HEE, 0);

    // 4) epilogue + bias path
    m_epilogue_kernel<<<32768, 256>>>(M, a, w, bk, bv);
    rcat_kernel<<<2048, 256>>>(bq, M, r);
    cvec_kernel<<<256, 256>>>(r, Wo, bo, c);
    conv_split<<<8192, 256>>>(M, bMT, bMT + hT1);

    // 5) T3_b[e][h*E+o2] = sum_o WqT[e][o] MT[o2][o]
    tgemm<false><<<dim3(4, 4, Bv * Hv), 256, SMEM_DYN>>>(
        bWqT, bWqT + hW, bMT, bMT + hT1, T, nullptr, Ev, HEv,
        Hv, EE, 0, EE, HEE, (long)Ev, EHE, 0);
    conv_split<<<8192, 256>>>(T, bT3, bT3 + hT3);

    // 6) NT_b[e2][e] = sum_f Wo[e2][f] T3[e][f]
    tgemm<false><<<dim3(4, 4, Bv), 256, SMEM_DYN>>>(
        bWo, bWo + hWo, bT3, bT3 + hT3, N, nullptr, HEv, Ev,
        1, 0, 0, 0, EHE, 0, EE, 0);
    conv_split<<<1024, 256>>>(N, bNT, bNT + hNT);

    // 7) out_b[s][e2] = sum_e q[s][e] NT[e2][e] + c_b[e2]
    tgemm<true><<<dim3(4, 16, Bv), 256, SMEM_DYN>>>(
        bq16, bq16 + hq, bNT, bNT + hNT, out, c, Ev, Ev,
        1, 0, SE, 0, EE, 0, SE, (long)Ev);
}

// round 5
// speedup vs baseline: 2.3380x; 1.3547x over previous
#include <cuda_runtime.h>
#include <cuda_bf16.h>
#include <cstdint>

#define Bv 4
#define Sv 2048
#define Ev 512
#define Hv 8
#define HEv 4096
#define EEv 262144

// fp32 intermediates
__device__ float g_T[(long)Bv * Hv * EEv];   // split-K partial scratch (16MB used)
__device__ float g_M[(long)Bv * Hv * EEv];   // MT fp32
__device__ float g_ksum[Bv * Ev], g_vsum[Bv * Ev];
__device__ float g_a[Bv * Hv * Ev], g_w[Bv * Hv * Ev];
__device__ float g_r[Bv * HEv], g_c[Bv * Ev];

// bf16 hi|lo buffers (lo at +half)
__device__ __nv_bfloat16 c_kT [2L * Bv * Ev * Sv];
__device__ __nv_bfloat16 c_vT [2L * Bv * Ev * Sv];
__device__ __nv_bfloat16 c_Wk [2L * Hv * EEv];
__device__ __nv_bfloat16 c_Wv [2L * Hv * EEv];
__device__ __nv_bfloat16 c_WqT[2L * Hv * EEv];
__device__ __nv_bfloat16 c_Wo [2L * Ev * HEv];
__device__ __nv_bfloat16 c_GT [2L * Bv * EEv];
__device__ __nv_bfloat16 c_T1 [2L * Bv * Hv * EEv];
__device__ __nv_bfloat16 c_MT [2L * Bv * Hv * EEv];
__device__ __nv_bfloat16 c_T3 [2L * Bv * Ev * HEv];
__device__ __nv_bfloat16 c_q  [2L * Bv * Sv * Ev];
__device__ __nv_bfloat16 c_NT [2L * Bv * EEv];

__device__ __forceinline__ uint32_t smem_u32(const void* p) {
    uint32_t a;
    asm("{ .reg .u64 t; cvta.to.shared.u64 t, %1; cvt.u32.u64 %0, t; }" : "=r"(a) : "l"(p));
    return a;
}
__device__ __forceinline__ void cpa16(uint32_t dst, const void* src) {
    asm volatile("cp.async.cg.shared.global [%0], [%1], 16;" :: "r"(dst), "l"(src));
}
__device__ __forceinline__ void ldsm4(uint32_t* r, uint32_t addr) {
    asm volatile("ldmatrix.sync.aligned.m8n8.x4.shared.b16 {%0,%1,%2,%3}, [%4];"
        : "=r"(r[0]), "=r"(r[1]), "=r"(r[2]), "=r"(r[3]) : "r"(addr));
}
__device__ __forceinline__ void mma_bf16(float* d, const uint32_t* a, const uint32_t* b) {
    asm volatile("mma.sync.aligned.m16n8k16.row.col.f32.bf16.bf16.f32 "
        "{%0,%1,%2,%3}, {%4,%5,%6,%7}, {%8,%9}, {%0,%1,%2,%3};"
        : "+f"(d[0]), "+f"(d[1]), "+f"(d[2]), "+f"(d[3])
        : "r"(a[0]), "r"(a[1]), "r"(a[2]), "r"(a[3]), "r"(b[0]), "r"(b[1]));
}
__device__ __forceinline__ __nv_bfloat162 hl_hi2(float x, float y) {
    __nv_bfloat162 r; r.x = __float2bfloat16(x); r.y = __float2bfloat16(y); return r;
}

#define SMEM_DYN 65536   // 2 stages x (A 16KB + B 16KB)

// MODE: 0 = fp32 out (optionally split-K partials), 1 = fp32 + bias, 2 = bf16 hi/lo out.
// C(m,n) = sum_k A(m,k)*B(n,k); A,B bf16 [rows][K] row-major, K % (64*nsplit) == 0.
// K tripled via hi/lo phases: [Ah*Bh, Ah*Bl, Al*Bh]. Tile 128x128, chunk 64.
template <int MODE>
__global__ void __launch_bounds__(256, 2)
tgemm(const __nv_bfloat16* __restrict__ Ahi, const __nv_bfloat16* __restrict__ Alo,
      const __nv_bfloat16* __restrict__ Bhi, const __nv_bfloat16* __restrict__ Blo,
      void* __restrict__ Cout, const void* __restrict__ aux,
      int K, int ldc, int zmod,
      long aS1, long aS2, long bS1, long bS2, long cS1, long cS2, long auxStride,
      int nsplit, long partStride)
{
    extern __shared__ __align__(128) char dsm[];
    uint32_t sbase = smem_u32(dsm);

    int tid = threadIdx.x, wid = tid >> 5, lane = tid & 31;
    int zPer = gridDim.z / nsplit;
    int split = blockIdx.z / zPer;
    int z = blockIdx.z % zPer;
    int zm = z % zmod, zd = z / zmod;
    Ahi += zm * aS1 + zd * aS2;  Alo += zm * aS1 + zd * aS2;
    Bhi += zm * bS1 + zd * bS2;  Blo += zm * bS1 + zd * bS2;
    int m0 = blockIdx.y * 128, n0 = blockIdx.x * 128;

    const int Ks = K / nsplit;          // K-range per split per phase
    const int CPP = Ks >> 6;            // chunks per phase
    const int NC = 3 * CPP;
    const int kofs = split * Ks;

    int srow = tid >> 3, scs = tid & 7;

    auto issue = [&](int c) {
        int phase = c / CPP;
        int kpos = kofs + ((c - phase * CPP) << 6);
        const __nv_bfloat16* pa = (phase < 2) ? Ahi : Alo;
        const __nv_bfloat16* pb = (phase == 1) ? Blo : Bhi;
        uint32_t sb = sbase + (uint32_t)((c & 1) << 15);
        #pragma unroll
        for (int t = 0; t < 8; t++) {
            int isB = t >> 2;
            int row = srow + ((t & 3) << 5);
            const __nv_bfloat16* src = (isB ? pb : pa) +
                (long)((isB ? n0 : m0) + row) * K + kpos + (scs << 3);
            uint32_t bo = (uint32_t)((row << 7) + (scs << 4));
            bo ^= (uint32_t)((row & 7) << 4);
            cpa16(sb + (uint32_t)(isB << 14) + bo, src);
        }
        asm volatile("cp.async.commit_group;" ::: "memory");
    };

    issue(0);
    issue(1);

    float acc[2][8][4] = {};
    int moff = (wid & 3) << 5;
    int noff = (wid >> 2) << 6;

    for (int c = 0; c < NC; c++) {
        if (c + 1 < NC) asm volatile("cp.async.wait_group 1;" ::: "memory");
        else            asm volatile("cp.async.wait_group 0;" ::: "memory");
        __syncthreads();
        uint32_t sb = sbase + (uint32_t)((c & 1) << 15);

        #pragma unroll
        for (int ks = 0; ks < 4; ks++) {
            uint32_t afr[2][4];
            #pragma unroll
            for (int i = 0; i < 2; i++) {
                int row = moff + (i << 4) + (lane & 15);
                int colb = (ks << 5) + ((lane >> 4) << 4);
                uint32_t bo = (uint32_t)((row << 7) + colb) ^ (uint32_t)((row & 7) << 4);
                ldsm4(afr[i], sb + bo);
            }
            uint32_t bfr[8][2];
            #pragma unroll
            for (int j2 = 0; j2 < 4; j2++) {
                int row = noff + (j2 << 4) + ((lane >> 4) << 3) + (lane & 7);
                int colb = (ks << 5) + (((lane >> 3) & 1) << 4);
                uint32_t bo = (uint32_t)((row << 7) + colb) ^ (uint32_t)((row & 7) << 4);
                uint32_t r[4];
                ldsm4(r, sb + 16384u + bo);
                bfr[2 * j2][0] = r[0]; bfr[2 * j2][1] = r[1];
                bfr[2 * j2 + 1][0] = r[2]; bfr[2 * j2 + 1][1] = r[3];
            }
            #pragma unroll
            for (int i = 0; i < 2; i++)
                #pragma unroll
                for (int j = 0; j < 8; j++)
                    mma_bf16(acc[i][j], afr[i], bfr[j]);
        }
        __syncthreads();
        if (c + 2 < NC) issue(c + 2);
    }

    int g = lane >> 2, t4 = lane & 3;
    if (MODE == 2) {
        __nv_bfloat16* hi = (__nv_bfloat16*)Cout + zm * cS1 + zd * cS2;
        __nv_bfloat16* lo = (__nv_bfloat16*)aux  + zm * cS1 + zd * cS2;
        #pragma unroll
        for (int i = 0; i < 2; i++) {
            int row0 = m0 + moff + (i << 4) + g;
            #pragma unroll
            for (int j = 0; j < 8; j++) {
                int col = n0 + noff + (j << 3) + (t4 << 1);
                #pragma unroll
                for (int rr = 0; rr < 2; rr++) {
                    long off = (long)(row0 + 8 * rr) * ldc + col;
                    float vx = acc[i][j][2 * rr], vy = acc[i][j][2 * rr + 1];
                    __nv_bfloat162 h = hl_hi2(vx, vy);
                    __nv_bfloat162 l = hl_hi2(vx - __bfloat162float(h.x), vy - __bfloat162float(h.y));
                    *reinterpret_cast<__nv_bfloat162*>(hi + off) = h;
                    *reinterpret_cast<__nv_bfloat162*>(lo + off) = l;
                }
            }
        }
    } else {
        float* C = (float*)Cout + zm * cS1 + zd * cS2 + (long)split * partStride;
        const float* bp = (MODE == 1) ? ((const float*)aux + zd * auxStride) : nullptr;
        #pragma unroll
        for (int i = 0; i < 2; i++) {
            int row0 = m0 + moff + (i << 4) + g;
            #pragma unroll
            for (int j = 0; j < 8; j++) {
                int col = n0 + noff + (j << 3) + (t4 << 1);
                float bx = 0.f, by = 0.f;
                if (MODE == 1) { float2 bb = *reinterpret_cast<const float2*>(bp + col); bx = bb.x; by = bb.y; }
                float2 o0 = make_float2(acc[i][j][0] + bx, acc[i][j][1] + by);
                float2 o1 = make_float2(acc[i][j][2] + bx, acc[i][j][3] + by);
                *reinterpret_cast<float2*>(&C[(long)row0 * ldc + col]) = o0;
                *reinterpret_cast<float2*>(&C[(long)(row0 + 8) * ldc + col]) = o1;
            }
        }
    }
}

// sum 4 split-K partials -> bf16 hi/lo. one float4 per thread.
__global__ void reduce4_hl(const float* __restrict__ parts, long pstride,
                           __nv_bfloat16* __restrict__ hi, __nv_bfloat16* __restrict__ lo) {
    long i = ((long)blockIdx.x * blockDim.x + threadIdx.x) * 4;
    float4 s = *reinterpret_cast<const float4*>(parts + i);
    #pragma unroll
    for (int p = 1; p < 4; p++) {
        float4 t = *reinterpret_cast<const float4*>(parts + p * pstride + i);
        s.x += t.x; s.y += t.y; s.z += t.z; s.w += t.w;
    }
    __nv_bfloat162 h0 = hl_hi2(s.x, s.y), h1 = hl_hi2(s.z, s.w);
    __nv_bfloat162 l0 = hl_hi2(s.x - __bfloat162float(h0.x), s.y - __bfloat162float(h0.y));
    __nv_bfloat162 l1 = hl_hi2(s.z - __bfloat162float(h1.x), s.w - __bfloat162float(h1.y));
    uint2 hp, lp;
    hp.x = *reinterpret_cast<uint32_t*>(&h0); hp.y = *reinterpret_cast<uint32_t*>(&h1);
    lp.x = *reinterpret_cast<uint32_t*>(&l0); lp.y = *reinterpret_cast<uint32_t*>(&l1);
    *reinterpret_cast<uint2*>(hi + i) = hp;
    *reinterpret_cast<uint2*>(lo + i) = lp;
}

// elementwise fp32 -> bf16 hi/lo
__global__ void conv_split(const float* __restrict__ src, __nv_bfloat16* __restrict__ hi,
                           __nv_bfloat16* __restrict__ lo) {
    long i = ((long)blockIdx.x * blockDim.x + threadIdx.x) * 4;
    float4 x = *reinterpret_cast<const float4*>(src + i);
    __nv_bfloat162 h0 = hl_hi2(x.x, x.y), h1 = hl_hi2(x.z, x.w);
    __nv_bfloat162 l0 = hl_hi2(x.x - __bfloat162float(h0.x), x.y - __bfloat162float(h0.y));
    __nv_bfloat162 l1 = hl_hi2(x.z - __bfloat162float(h1.x), x.w - __bfloat162float(h1.y));
    uint2 hp, lp;
    hp.x = *reinterpret_cast<uint32_t*>(&h0); hp.y = *reinterpret_cast<uint32_t*>(&h1);
    lp.x = *reinterpret_cast<uint32_t*>(&l0); lp.y = *reinterpret_cast<uint32_t*>(&l1);
    *reinterpret_cast<uint2*>(hi + i) = hp;
    *reinterpret_cast<uint2*>(lo + i) = lp;
}

// dst[r][k] = src[k][r], split. block (32,8); grid (srcRows/32, dstRows/32, Z)
__global__ void conv_tsplit(const float* __restrict__ src, __nv_bfloat16* __restrict__ hi,
                            __nv_bfloat16* __restrict__ lo,
                            int srcLd, long srcZ, int dstLd, long dstZ) {
    __shared__ float tile[32][33];
    int zz = blockIdx.z;
    src += (long)zz * srcZ;
    long dz = (long)zz * dstZ;
    int k0 = blockIdx.x * 32, r0 = blockIdx.y * 32;
    int tx = threadIdx.x, ty = threadIdx.y;
    #pragma unroll
    for (int i = 0; i < 4; i++)
        tile[ty + 8 * i][tx] = src[(long)(k0 + ty + 8 * i) * srcLd + r0 + tx];
    __syncthreads();
    #pragma unroll
    for (int i = 0; i < 4; i++) {
        int r = r0 + ty + 8 * i, kk = k0 + tx;
        float x = tile[tx][ty + 8 * i];
        __nv_bfloat16 h = __float2bfloat16(x);
        hi[dz + (long)r * dstLd + kk] = h;
        lo[dz + (long)r * dstLd + kk] = __float2bfloat16(x - __bfloat162float(h));
    }
}

__global__ void colsum_kernel(const float* __restrict__ k, const float* __restrict__ v,
                              float* __restrict__ ks, float* __restrict__ vs) {
    int b = blockIdx.x, e = threadIdx.x;
    const float* kb = k + (long)b * Sv * Ev;
    const float* vb = v + (long)b * Sv * Ev;
    float sk = 0.f, sv = 0.f;
    for (int s = 0; s < Sv; s++) { sk += kb[(long)s * Ev + e]; sv += vb[(long)s * Ev + e]; }
    ks[b * Ev + e] = sk; vs[b * Ev + e] = sv;
}
__global__ void rowdot_kernel(const float* __restrict__ W, const float* __restrict__ x,
                              float* __restrict__ out) {
    int gw = (blockIdx.x * blockDim.x + threadIdx.x) >> 5, lane = threadIdx.x & 31;
    int o = gw & (Ev - 1), zz = gw >> 9, h = zz & (Hv - 1), b = zz >> 3;
    const float* wr = W + (long)(h * Ev + o) * Ev;
    const float* xr = x + b * Ev;
    float s = 0.f;
    for (int e = lane; e < Ev; e += 32) s += wr[e] * xr[e];
    #pragma unroll
    for (int off = 16; off > 0; off >>= 1) s += __shfl_xor_sync(0xFFFFFFFFu, s, off);
    if (lane == 0) out[gw] = s;
}
// MT layout [z][o2][o1]; writes fp32 (for rcat) + bf16 hi/lo (for next GEMM)
__global__ void m_epilogue_kernel(float* __restrict__ MT, const float* __restrict__ a,
                                  const float* __restrict__ w, const float* __restrict__ bk,
                                  const float* __restrict__ bv,
                                  __nv_bfloat16* __restrict__ hi, __nv_bfloat16* __restrict__ lo) {
    long idx = (long)blockIdx.x * blockDim.x + threadIdx.x;
    int o1 = (int)(idx & (Ev - 1));
    int o2 = (int)((idx >> 9) & (Ev - 1));
    int zz = (int)(idx >> 18);
    int h = zz & (Hv - 1);
    float bk1 = bk[h * Ev + o1], bv2 = bv[h * Ev + o2];
    float t = MT[idx] + a[zz * Ev + o1] * bv2 + bk1 * w[zz * Ev + o2] + (float)Sv * bk1 * bv2;
    t *= (1.0f / (float)Ev);
    MT[idx] = t;
    __nv_bfloat16 hb = __float2bfloat16(t);
    hi[idx] = hb;
    lo[idx] = __float2bfloat16(t - __bfloat162float(hb));
}
__global__ void rcat_kernel(const float* __restrict__ bq, const float* __restrict__ MT,
                            float* __restrict__ r) {
    int gw = (blockIdx.x * blockDim.x + threadIdx.x) >> 5, lane = threadIdx.x & 31;
    int o2 = gw & (Ev - 1), zz = gw >> 9, h = zz & (Hv - 1);
    const float* Mr = MT + (long)zz * EEv + (long)o2 * Ev;
    const float* bqh = bq + h * Ev;
    float s = 0.f;
    for (int o = lane; o < Ev; o += 32) s += bqh[o] * Mr[o];
    #pragma unroll
    for (int off = 16; off > 0; off >>= 1) s += __shfl_xor_sync(0xFFFFFFFFu, s, off);
    if (lane == 0) r[gw] = s;
}
__global__ void cvec_kernel(const float* __restrict__ r, const float* __restrict__ Wo,
                            const float* __restrict__ bo, float* __restrict__ c) {
    int gw = (blockIdx.x * blockDim.x + threadIdx.x) >> 5, lane = threadIdx.x & 31;
    int e2 = gw & (Ev - 1), b = gw >> 9;
    const float* rr = r + b * HEv;
    const float* wr = Wo + (long)e2 * HEv;
    float s = 0.f;
    for (int f = lane; f < HEv; f += 32) s += rr[f] * wr[f];
    #pragma unroll
    for (int off = 16; off > 0; off >>= 1) s += __shfl_xor_sync(0xFFFFFFFFu, s, off);
    if (lane == 0) c[gw] = s + bo[e2];
}

extern "C" void kernel_launch(void* const* d_in, const int* in_sizes, int n_in,
                              void* d_out, int out_size) {
    const float* q  = (const float*)d_in[0];
    const float* k  = (const float*)d_in[1];
    const float* v  = (const float*)d_in[2];
    const float* Wq = (const float*)d_in[3];
    const float* bq = (const float*)d_in[4];
    const float* Wk = (const float*)d_in[5];
    const float* bk = (const float*)d_in[6];
    const float* Wv = (const float*)d_in[7];
    const float* bv = (const float*)d_in[8];
    const float* Wo = (const float*)d_in[9];
    const float* bo = (const float*)d_in[10];
    float* out = (float*)d_out;

    float *Tp, *M, *ksum, *vsum, *a, *w, *r, *c;
    cudaGetSymbolAddress((void**)&Tp, g_T);
    cudaGetSymbolAddress((void**)&M, g_M);
    cudaGetSymbolAddress((void**)&ksum, g_ksum);
    cudaGetSymbolAddress((void**)&vsum, g_vsum);
    cudaGetSymbolAddress((void**)&a, g_a);
    cudaGetSymbolAddress((void**)&w, g_w);
    cudaGetSymbolAddress((void**)&r, g_r);
    cudaGetSymbolAddress((void**)&c, g_c);

    __nv_bfloat16 *kT, *vT, *bWk, *bWv, *bWqT, *bWo, *bGT, *bT1, *bMT, *bT3, *bq16, *bNT;
    cudaGetSymbolAddress((void**)&kT, c_kT);
    cudaGetSymbolAddress((void**)&vT, c_vT);
    cudaGetSymbolAddress((void**)&bWk, c_Wk);
    cudaGetSymbolAddress((void**)&bWv, c_Wv);
    cudaGetSymbolAddress((void**)&bWqT, c_WqT);
    cudaGetSymbolAddress((void**)&bWo, c_Wo);
    cudaGetSymbolAddress((void**)&bGT, c_GT);
    cudaGetSymbolAddress((void**)&bT1, c_T1);
    cudaGetSymbolAddress((void**)&bMT, c_MT);
    cudaGetSymbolAddress((void**)&bT3, c_T3);
    cudaGetSymbolAddress((void**)&bq16, c_q);
    cudaGetSymbolAddress((void**)&bNT, c_NT);

    cudaFuncSetAttribute(tgemm<0>, cudaFuncAttributeMaxDynamicSharedMemorySize, SMEM_DYN);
    cudaFuncSetAttribute(tgemm<1>, cudaFuncAttributeMaxDynamicSharedMemorySize, SMEM_DYN);
    cudaFuncSetAttribute(tgemm<2>, cudaFuncAttributeMaxDynamicSharedMemorySize, SMEM_DYN);

    const long ES = (long)Ev * Sv, EE = EEv, HEE = (long)Hv * EEv;
    const long SE = (long)Sv * Ev, EHE = (long)Ev * HEv;
    const long hKT = (long)Bv * ES, hW = (long)Hv * EEv, hWo = (long)Ev * HEv;
    const long hGT = (long)Bv * EEv, hT1 = (long)Bv * Hv * EEv, hT3 = (long)Bv * EHE;
    const long hq = (long)Bv * SE, hNT = (long)Bv * EEv;
    const long PART = (long)Bv * EEv;   // partial stride (1M floats)

    // fp32 prep
    colsum_kernel<<<Bv, Ev>>>(k, v, ksum, vsum);
    rowdot_kernel<<<2048, 256>>>(Wk, ksum, a);
    rowdot_kernel<<<2048, 256>>>(Wv, vsum, w);

    // conversions of inputs
    dim3 tb(32, 8);
    conv_tsplit<<<dim3(64, 16, Bv), tb>>>(k, kT, kT + hKT, Ev, SE, Sv, ES);
    conv_tsplit<<<dim3(64, 16, Bv), tb>>>(v, vT, vT + hKT, Ev, SE, Sv, ES);
    conv_tsplit<<<dim3(16, 16, Hv), tb>>>(Wq, bWqT, bWqT + hW, Ev, EE, Ev, EE);
    conv_split<<<2048, 256>>>(Wk, bWk, bWk + hW);
    conv_split<<<2048, 256>>>(Wv, bWv, bWv + hW);
    conv_split<<<2048, 256>>>(Wo, bWo, bWo + hWo);
    conv_split<<<4096, 256>>>(q, bq16, bq16 + hq);

    // 1) GT_b[e2][e1] = sum_s v[s][e2] k[s][e1]   (split-K=4 -> reduce to bf16)
    tgemm<0><<<dim3(4, 4, Bv * 4), 256, SMEM_DYN>>>(
        vT, vT + hKT, kT, kT + hKT, Tp, nullptr, Sv, Ev,
        1, 0, ES, 0, ES, 0, EE, 0, 4, PART);
    reduce4_hl<<<1024, 256>>>(Tp, PART, bGT, bGT + hGT);

    // 2) T1_z[o1][e2] = sum_e Wk[o1][e] GT[e2][e]   -> bf16 hi/lo direct
    tgemm<2><<<dim3(4, 4, Bv * Hv), 256, SMEM_DYN>>>(
        bWk, bWk + hW, bGT, bGT + hGT, bT1, bT1 + hT1, Ev, Ev,
        Hv, EE, 0, 0, EE, EE, HEE, 0, 1, 0);

    // 3) MT_z[o2][o1] = sum_e2 Wv[o2][e2] T1[o1][e2]   -> fp32
    tgemm<0><<<dim3(4, 4, Bv * Hv), 256, SMEM_DYN>>>(
        bWv, bWv + hW, bT1, bT1 + hT1, M, nullptr, Ev, Ev,
        Hv, EE, 0, EE, HEE, EE, HEE, 0, 1, 0);

    // 4) epilogue (fp32 + bf16 hi/lo) + bias path
    m_epilogue_kernel<<<32768, 256>>>(M, a, w, bk, bv, bMT, bMT + hT1);
    rcat_kernel<<<2048, 256>>>(bq, M, r);
    cvec_kernel<<<256, 256>>>(r, Wo, bo, c);

    // 5) T3_b[e][h*E+o2] = sum_o WqT[e][o] MT[o2][o]   -> bf16 hi/lo direct
    tgemm<2><<<dim3(4, 4, Bv * Hv), 256, SMEM_DYN>>>(
        bWqT, bWqT + hW, bMT, bMT + hT1, bT3, bT3 + hT3, Ev, HEv,
        Hv, EE, 0, EE, HEE, (long)Ev, EHE, 0, 1, 0);

    // 6) NT_b[e2][e] = sum_f Wo[e2][f] T3[e][f]   (split-K=4 -> reduce to bf16)
    tgemm<0><<<dim3(4, 4, Bv * 4), 256, SMEM_DYN>>>(
        bWo, bWo + hWo, bT3, bT3 + hT3, Tp, nullptr, HEv, Ev,
        1, 0, 0, 0, EHE, 0, EE, 0, 4, PART);
    reduce4_hl<<<1024, 256>>>(Tp, PART, bNT, bNT + hNT);

    // 7) out_b[s][e2] = sum_e q[s][e] NT[e2][e] + c_b[e2]
    tgemm<1><<<dim3(4, 16, Bv), 256, SMEM_DYN>>>(
        bq16, bq16 + hq, bNT, bNT + hNT, out, c, Ev, Ev,
        1, 0, SE, 0, EE, 0, SE, (long)Ev, 1, 0);
}

// round 6
// speedup vs baseline: 2.4243x; 1.0369x over previous
#include <cuda_runtime.h>
#include <cuda_bf16.h>
#include <cstdint>

#define Bv 4
#define Sv 2048
#define Ev 512
#define Hv 8
#define HEv 4096
#define EEv 262144

// fp32 intermediates
__device__ float g_T[(long)Bv * Hv * EEv];   // split-K partial scratch
__device__ float g_M[(long)Bv * Hv * EEv];   // MT fp32
__device__ float g_ksum[Bv * Ev], g_vsum[Bv * Ev];
__device__ float g_a[Bv * Hv * Ev], g_w[Bv * Hv * Ev];
__device__ float g_r[Bv * HEv], g_c[Bv * Ev];

// bf16 hi|lo buffers (lo at +half)
__device__ __nv_bfloat16 c_kT [2L * Bv * Ev * Sv];
__device__ __nv_bfloat16 c_vT [2L * Bv * Ev * Sv];
__device__ __nv_bfloat16 c_Wk [2L * Hv * EEv];
__device__ __nv_bfloat16 c_Wv [2L * Hv * EEv];
__device__ __nv_bfloat16 c_WqT[2L * Hv * EEv];
__device__ __nv_bfloat16 c_Wo [2L * Ev * HEv];
__device__ __nv_bfloat16 c_GT [2L * Bv * EEv];
__device__ __nv_bfloat16 c_T1 [2L * Bv * Hv * EEv];
__device__ __nv_bfloat16 c_MT [2L * Bv * Hv * EEv];
__device__ __nv_bfloat16 c_T3 [2L * Bv * Ev * HEv];
__device__ __nv_bfloat16 c_q  [2L * Bv * Sv * Ev];
__device__ __nv_bfloat16 c_NT [2L * Bv * EEv];

__device__ __forceinline__ uint32_t smem_u32(const void* p) {
    uint32_t a;
    asm("{ .reg .u64 t; cvta.to.shared.u64 t, %1; cvt.u32.u64 %0, t; }" : "=r"(a) : "l"(p));
    return a;
}
__device__ __forceinline__ void cpa16(uint32_t dst, const void* src) {
    asm volatile("cp.async.cg.shared.global [%0], [%1], 16;" :: "r"(dst), "l"(src));
}
__device__ __forceinline__ void ldsm4(uint32_t* r, uint32_t addr) {
    asm volatile("ldmatrix.sync.aligned.m8n8.x4.shared.b16 {%0,%1,%2,%3}, [%4];"
        : "=r"(r[0]), "=r"(r[1]), "=r"(r[2]), "=r"(r[3]) : "r"(addr));
}
__device__ __forceinline__ void mma_bf16(float* d, const uint32_t* a, const uint32_t* b) {
    asm volatile("mma.sync.aligned.m16n8k16.row.col.f32.bf16.bf16.f32 "
        "{%0,%1,%2,%3}, {%4,%5,%6,%7}, {%8,%9}, {%0,%1,%2,%3};"
        : "+f"(d[0]), "+f"(d[1]), "+f"(d[2]), "+f"(d[3])
        : "r"(a[0]), "r"(a[1]), "r"(a[2]), "r"(a[3]), "r"(b[0]), "r"(b[1]));
}
__device__ __forceinline__ __nv_bfloat162 hl_hi2(float x, float y) {
    __nv_bfloat162 r; r.x = __float2bfloat16(x); r.y = __float2bfloat16(y); return r;
}

#define STAGE 32768
#define SMEM_DYN (3 * STAGE)   // 3 stages x (A 16KB | B 16KB)

// MODE: 0 = fp32 (split-K partials), 1 = fp32 + bias, 2 = bf16 hi/lo,
//       3 = fused M epilogue (fp32 + bf16 hi/lo + rank-1 corrections, x 1/E)
// C(m,n) = sum_k A(m,k)*B(n,k); A,B bf16 [rows][K] row-major, K % (64*nsplit) == 0.
// K tripled via hi/lo phases: [Ah*Bh, Ah*Bl, Al*Bh]. Tile 128x128, chunk 64, 3-stage pipe.
template <int MODE>
__global__ void __launch_bounds__(256, 2)
tgemm(const __nv_bfloat16* __restrict__ Ahi, const __nv_bfloat16* __restrict__ Alo,
      const __nv_bfloat16* __restrict__ Bhi, const __nv_bfloat16* __restrict__ Blo,
      void* __restrict__ Cout, const void* __restrict__ aux, void* __restrict__ out2,
      const float* __restrict__ e_a, const float* __restrict__ e_w,
      const float* __restrict__ e_bk, const float* __restrict__ e_bv,
      int K, int ldc, int zmod,
      long aS1, long aS2, long bS1, long bS2, long cS1, long cS2, long auxStride,
      int nsplit, long partStride)
{
    extern __shared__ __align__(128) char dsm[];
    uint32_t sbase = smem_u32(dsm);

    int tid = threadIdx.x, wid = tid >> 5, lane = tid & 31;
    int zPer = gridDim.z / nsplit;
    int split = blockIdx.z / zPer;
    int z = blockIdx.z % zPer;
    int zm = z % zmod, zd = z / zmod;
    Ahi += zm * aS1 + zd * aS2;  Alo += zm * aS1 + zd * aS2;
    Bhi += zm * bS1 + zd * bS2;  Blo += zm * bS1 + zd * bS2;
    int m0 = blockIdx.y * 128, n0 = blockIdx.x * 128;

    const int Ks = K / nsplit;
    const int CPP = Ks >> 6;
    const int NC = 3 * CPP;
    const int kofs = split * Ks;

    int srow = tid >> 3, scs = tid & 7;

    auto issue = [&](int c) {
        int phase = c / CPP;
        int kpos = kofs + ((c - phase * CPP) << 6);
        const __nv_bfloat16* pa = (phase < 2) ? Ahi : Alo;
        const __nv_bfloat16* pb = (phase == 1) ? Blo : Bhi;
        uint32_t sb = sbase + (uint32_t)((c % 3) * STAGE);
        #pragma unroll
        for (int t = 0; t < 8; t++) {
            int isB = t >> 2;
            int row = srow + ((t & 3) << 5);
            const __nv_bfloat16* src = (isB ? pb : pa) +
                (long)((isB ? n0 : m0) + row) * K + kpos + (scs << 3);
            uint32_t bo = (uint32_t)((row << 7) + (scs << 4));
            bo ^= (uint32_t)((row & 7) << 4);
            cpa16(sb + (uint32_t)(isB << 14) + bo, src);
        }
        asm volatile("cp.async.commit_group;" ::: "memory");
    };

    issue(0);
    issue(1);

    float acc[2][8][4] = {};
    int moff = (wid & 3) << 5;
    int noff = (wid >> 2) << 6;

    for (int c = 0; c < NC; c++) {
        if (c + 1 < NC) asm volatile("cp.async.wait_group 1;" ::: "memory");
        else            asm volatile("cp.async.wait_group 0;" ::: "memory");
        __syncthreads();
        if (c + 2 < NC) issue(c + 2);   // overlaps with compute below; stage (c+2)%3 is free
        uint32_t sb = sbase + (uint32_t)((c % 3) * STAGE);

        #pragma unroll
        for (int ks = 0; ks < 4; ks++) {
            uint32_t afr[2][4];
            #pragma unroll
            for (int i = 0; i < 2; i++) {
                int row = moff + (i << 4) + (lane & 15);
                int colb = (ks << 5) + ((lane >> 4) << 4);
                uint32_t bo = (uint32_t)((row << 7) + colb) ^ (uint32_t)((row & 7) << 4);
                ldsm4(afr[i], sb + bo);
            }
            uint32_t bfr[8][2];
            #pragma unroll
            for (int j2 = 0; j2 < 4; j2++) {
                int row = noff + (j2 << 4) + ((lane >> 4) << 3) + (lane & 7);
                int colb = (ks << 5) + (((lane >> 3) & 1) << 4);
                uint32_t bo = (uint32_t)((row << 7) + colb) ^ (uint32_t)((row & 7) << 4);
                uint32_t r[4];
                ldsm4(r, sb + 16384u + bo);
                bfr[2 * j2][0] = r[0]; bfr[2 * j2][1] = r[1];
                bfr[2 * j2 + 1][0] = r[2]; bfr[2 * j2 + 1][1] = r[3];
            }
            #pragma unroll
            for (int i = 0; i < 2; i++)
                #pragma unroll
                for (int j = 0; j < 8; j++)
                    mma_bf16(acc[i][j], afr[i], bfr[j]);
        }
        // no trailing barrier: next iteration's wait+sync provides it
    }

    int g = lane >> 2, t4 = lane & 3;
    if (MODE == 2) {
        __nv_bfloat16* hi = (__nv_bfloat16*)Cout + zm * cS1 + zd * cS2;
        __nv_bfloat16* lo = (__nv_bfloat16*)aux  + zm * cS1 + zd * cS2;
        #pragma unroll
        for (int i = 0; i < 2; i++) {
            int row0 = m0 + moff + (i << 4) + g;
            #pragma unroll
            for (int j = 0; j < 8; j++) {
                int col = n0 + noff + (j << 3) + (t4 << 1);
                #pragma unroll
                for (int rr = 0; rr < 2; rr++) {
                    long off = (long)(row0 + 8 * rr) * ldc + col;
                    float vx = acc[i][j][2 * rr], vy = acc[i][j][2 * rr + 1];
                    __nv_bfloat162 h = hl_hi2(vx, vy);
                    __nv_bfloat162 l = hl_hi2(vx - __bfloat162float(h.x), vy - __bfloat162float(h.y));
                    *reinterpret_cast<__nv_bfloat162*>(hi + off) = h;
                    *reinterpret_cast<__nv_bfloat162*>(lo + off) = l;
                }
            }
        }
    } else if (MODE == 3) {
        // t(m,n) = (acc + a[z,n]*bv[h,m] + bk[h,n]*w[z,m] + S*bk[h,n]*bv[h,m]) / E
        const float invE = 1.0f / (float)Ev;
        float* Mo = (float*)Cout + zm * cS1 + zd * cS2;
        __nv_bfloat16* hi = (__nv_bfloat16*)aux  + zm * cS1 + zd * cS2;
        __nv_bfloat16* lo = (__nv_bfloat16*)out2 + zm * cS1 + zd * cS2;
        const float* av = e_a + (long)z * Ev;     // z = b*Hv + h (zmod == Hv)
        const float* wv = e_w + (long)z * Ev;
        const float* bkv = e_bk + (long)zm * Ev;
        const float* bvv = e_bv + (long)zm * Ev;
        #pragma unroll
        for (int i = 0; i < 2; i++) {
            int row0 = m0 + moff + (i << 4) + g;
            float bv0 = bvv[row0], bv1 = bvv[row0 + 8];
            float w0 = wv[row0],  w1 = wv[row0 + 8];
            #pragma unroll
            for (int j = 0; j < 8; j++) {
                int col = n0 + noff + (j << 3) + (t4 << 1);
                float2 a2  = *reinterpret_cast<const float2*>(av + col);
                float2 bk2 = *reinterpret_cast<const float2*>(bkv + col);
                float vals[2][2];
                vals[0][0] = (acc[i][j][0] + a2.x * bv0 + bk2.x * w0 + (float)Sv * bk2.x * bv0) * invE;
                vals[0][1] = (acc[i][j][1] + a2.y * bv0 + bk2.y * w0 + (float)Sv * bk2.y * bv0) * invE;
                vals[1][0] = (acc[i][j][2] + a2.x * bv1 + bk2.x * w1 + (float)Sv * bk2.x * bv1) * invE;
                vals[1][1] = (acc[i][j][3] + a2.y * bv1 + bk2.y * w1 + (float)Sv * bk2.y * bv1) * invE;
                #pragma unroll
                for (int rr = 0; rr < 2; rr++) {
                    long off = (long)(row0 + 8 * rr) * ldc + col;
                    *reinterpret_cast<float2*>(Mo + off) = make_float2(vals[rr][0], vals[rr][1]);
                    __nv_bfloat162 h = hl_hi2(vals[rr][0], vals[rr][1]);
                    __nv_bfloat162 l = hl_hi2(vals[rr][0] - __bfloat162float(h.x),
                                              vals[rr][1] - __bfloat162float(h.y));
                    *reinterpret_cast<__nv_bfloat162*>(hi + off) = h;
                    *reinterpret_cast<__nv_bfloat162*>(lo + off) = l;
                }
            }
        }
    } else {
        float* C = (float*)Cout + zm * cS1 + zd * cS2 + (long)split * partStride;
        const float* bp = (MODE == 1) ? ((const float*)aux + zd * auxStride) : nullptr;
        #pragma unroll
        for (int i = 0; i < 2; i++) {
            int row0 = m0 + moff + (i << 4) + g;
            #pragma unroll
            for (int j = 0; j < 8; j++) {
                int col = n0 + noff + (j << 3) + (t4 << 1);
                float bx = 0.f, by = 0.f;
                if (MODE == 1) { float2 bb = *reinterpret_cast<const float2*>(bp + col); bx = bb.x; by = bb.y; }
                float2 o0 = make_float2(acc[i][j][0] + bx, acc[i][j][1] + by);
                float2 o1 = make_float2(acc[i][j][2] + bx, acc[i][j][3] + by);
                *reinterpret_cast<float2*>(&C[(long)row0 * ldc + col]) = o0;
                *reinterpret_cast<float2*>(&C[(long)(row0 + 8) * ldc + col]) = o1;
            }
        }
    }
}

// sum 4 split-K partials -> bf16 hi/lo
__global__ void reduce4_hl(const float* __restrict__ parts, long pstride,
                           __nv_bfloat16* __restrict__ hi, __nv_bfloat16* __restrict__ lo) {
    long i = ((long)blockIdx.x * blockDim.x + threadIdx.x) * 4;
    float4 s = *reinterpret_cast<const float4*>(parts + i);
    #pragma unroll
    for (int p = 1; p < 4; p++) {
        float4 t = *reinterpret_cast<const float4*>(parts + p * pstride + i);
        s.x += t.x; s.y += t.y; s.z += t.z; s.w += t.w;
    }
    __nv_bfloat162 h0 = hl_hi2(s.x, s.y), h1 = hl_hi2(s.z, s.w);
    __nv_bfloat162 l0 = hl_hi2(s.x - __bfloat162float(h0.x), s.y - __bfloat162float(h0.y));
    __nv_bfloat162 l1 = hl_hi2(s.z - __bfloat162float(h1.x), s.w - __bfloat162float(h1.y));
    uint2 hp, lp;
    hp.x = *reinterpret_cast<uint32_t*>(&h0); hp.y = *reinterpret_cast<uint32_t*>(&h1);
    lp.x = *reinterpret_cast<uint32_t*>(&l0); lp.y = *reinterpret_cast<uint32_t*>(&l1);
    *reinterpret_cast<uint2*>(hi + i) = hp;
    *reinterpret_cast<uint2*>(lo + i) = lp;
}

__global__ void conv_split(const float* __restrict__ src, __nv_bfloat16* __restrict__ hi,
                           __nv_bfloat16* __restrict__ lo) {
    long i = ((long)blockIdx.x * blockDim.x + threadIdx.x) * 4;
    float4 x = *reinterpret_cast<const float4*>(src + i);
    __nv_bfloat162 h0 = hl_hi2(x.x, x.y), h1 = hl_hi2(x.z, x.w);
    __nv_bfloat162 l0 = hl_hi2(x.x - __bfloat162float(h0.x), x.y - __bfloat162float(h0.y));
    __nv_bfloat162 l1 = hl_hi2(x.z - __bfloat162float(h1.x), x.w - __bfloat162float(h1.y));
    uint2 hp, lp;
    hp.x = *reinterpret_cast<uint32_t*>(&h0); hp.y = *reinterpret_cast<uint32_t*>(&h1);
    lp.x = *reinterpret_cast<uint32_t*>(&l0); lp.y = *reinterpret_cast<uint32_t*>(&l1);
    *reinterpret_cast<uint2*>(hi + i) = hp;
    *reinterpret_cast<uint2*>(lo + i) = lp;
}

__global__ void conv_tsplit(const float* __restrict__ src, __nv_bfloat16* __restrict__ hi,
                            __nv_bfloat16* __restrict__ lo,
                            int srcLd, long srcZ, int dstLd, long dstZ) {
    __shared__ float tile[32][33];
    int zz = blockIdx.z;
    src += (long)zz * srcZ;
    long dz = (long)zz * dstZ;
    int k0 = blockIdx.x * 32, r0 = blockIdx.y * 32;
    int tx = threadIdx.x, ty = threadIdx.y;
    #pragma unroll
    for (int i = 0; i < 4; i++)
        tile[ty + 8 * i][tx] = src[(long)(k0 + ty + 8 * i) * srcLd + r0 + tx];
    __syncthreads();
    #pragma unroll
    for (int i = 0; i < 4; i++) {
        int r = r0 + ty + 8 * i, kk = k0 + tx;
        float x = tile[tx][ty + 8 * i];
        __nv_bfloat16 h = __float2bfloat16(x);
        hi[dz + (long)r * dstLd + kk] = h;
        lo[dz + (long)r * dstLd + kk] = __float2bfloat16(x - __bfloat162float(h));
    }
}

__global__ void colsum_kernel(const float* __restrict__ k, const float* __restrict__ v,
                              float* __restrict__ ks, float* __restrict__ vs) {
    int b = blockIdx.x, e = threadIdx.x;
    const float* kb = k + (long)b * Sv * Ev;
    const float* vb = v + (long)b * Sv * Ev;
    float sk = 0.f, sv = 0.f;
    for (int s = 0; s < Sv; s++) { sk += kb[(long)s * Ev + e]; sv += vb[(long)s * Ev + e]; }
    ks[b * Ev + e] = sk; vs[b * Ev + e] = sv;
}
__global__ void rowdot_kernel(const float* __restrict__ W, const float* __restrict__ x,
                              float* __restrict__ out) {
    int gw = (blockIdx.x * blockDim.x + threadIdx.x) >> 5, lane = threadIdx.x & 31;
    int o = gw & (Ev - 1), zz = gw >> 9, h = zz & (Hv - 1), b = zz >> 3;
    const float* wr = W + (long)(h * Ev + o) * Ev;
    const float* xr = x + b * Ev;
    float s = 0.f;
    for (int e = lane; e < Ev; e += 32) s += wr[e] * xr[e];
    #pragma unroll
    for (int off = 16; off > 0; off >>= 1) s += __shfl_xor_sync(0xFFFFFFFFu, s, off);
    if (lane == 0) out[gw] = s;
}
__global__ void rcat_kernel(const float* __restrict__ bq, const float* __restrict__ MT,
                            float* __restrict__ r) {
    int gw = (blockIdx.x * blockDim.x + threadIdx.x) >> 5, lane = threadIdx.x & 31;
    int o2 = gw & (Ev - 1), zz = gw >> 9, h = zz & (Hv - 1);
    const float* Mr = MT + (long)zz * EEv + (long)o2 * Ev;
    const float* bqh = bq + h * Ev;
    float s = 0.f;
    for (int o = lane; o < Ev; o += 32) s += bqh[o] * Mr[o];
    #pragma unroll
    for (int off = 16; off > 0; off >>= 1) s += __shfl_xor_sync(0xFFFFFFFFu, s, off);
    if (lane == 0) r[gw] = s;
}
__global__ void cvec_kernel(const float* __restrict__ r, const float* __restrict__ Wo,
                            const float* __restrict__ bo, float* __restrict__ c) {
    int gw = (blockIdx.x * blockDim.x + threadIdx.x) >> 5, lane = threadIdx.x & 31;
    int e2 = gw & (Ev - 1), b = gw >> 9;
    const float* rr = r + b * HEv;
    const float* wr = Wo + (long)e2 * HEv;
    float s = 0.f;
    for (int f = lane; f < HEv; f += 32) s += rr[f] * wr[f];
    #pragma unroll
    for (int off = 16; off > 0; off >>= 1) s += __shfl_xor_sync(0xFFFFFFFFu, s, off);
    if (lane == 0) c[gw] = s + bo[e2];
}

extern "C" void kernel_launch(void* const* d_in, const int* in_sizes, int n_in,
                              void* d_out, int out_size) {
    const float* q  = (const float*)d_in[0];
    const float* k  = (const float*)d_in[1];
    const float* v  = (const float*)d_in[2];
    const float* Wq = (const float*)d_in[3];
    const float* bq = (const float*)d_in[4];
    const float* Wk = (const float*)d_in[5];
    const float* bk = (const float*)d_in[6];
    const float* Wv = (const float*)d_in[7];
    const float* bv = (const float*)d_in[8];
    const float* Wo = (const float*)d_in[9];
    const float* bo = (const float*)d_in[10];
    float* out = (float*)d_out;

    float *Tp, *M, *ksum, *vsum, *a, *w, *r, *c;
    cudaGetSymbolAddress((void**)&Tp, g_T);
    cudaGetSymbolAddress((void**)&M, g_M);
    cudaGetSymbolAddress((void**)&ksum, g_ksum);
    cudaGetSymbolAddress((void**)&vsum, g_vsum);
    cudaGetSymbolAddress((void**)&a, g_a);
    cudaGetSymbolAddress((void**)&w, g_w);
    cudaGetSymbolAddress((void**)&r, g_r);
    cudaGetSymbolAddress((void**)&c, g_c);

    __nv_bfloat16 *kT, *vT, *bWk, *bWv, *bWqT, *bWo, *bGT, *bT1, *bMT, *bT3, *bq16, *bNT;
    cudaGetSymbolAddress((void**)&kT, c_kT);
    cudaGetSymbolAddress((void**)&vT, c_vT);
    cudaGetSymbolAddress((void**)&bWk, c_Wk);
    cudaGetSymbolAddress((void**)&bWv, c_Wv);
    cudaGetSymbolAddress((void**)&bWqT, c_WqT);
    cudaGetSymbolAddress((void**)&bWo, c_Wo);
    cudaGetSymbolAddress((void**)&bGT, c_GT);
    cudaGetSymbolAddress((void**)&bT1, c_T1);
    cudaGetSymbolAddress((void**)&bMT, c_MT);
    cudaGetSymbolAddress((void**)&bT3, c_T3);
    cudaGetSymbolAddress((void**)&bq16, c_q);
    cudaGetSymbolAddress((void**)&bNT, c_NT);

    cudaFuncSetAttribute(tgemm<0>, cudaFuncAttributeMaxDynamicSharedMemorySize, SMEM_DYN);
    cudaFuncSetAttribute(tgemm<1>, cudaFuncAttributeMaxDynamicSharedMemorySize, SMEM_DYN);
    cudaFuncSetAttribute(tgemm<2>, cudaFuncAttributeMaxDynamicSharedMemorySize, SMEM_DYN);
    cudaFuncSetAttribute(tgemm<3>, cudaFuncAttributeMaxDynamicSharedMemorySize, SMEM_DYN);

    const long ES = (long)Ev * Sv, EE = EEv, HEE = (long)Hv * EEv;
    const long SE = (long)Sv * Ev, EHE = (long)Ev * HEv;
    const long hKT = (long)Bv * ES, hW = (long)Hv * EEv, hWo = (long)Ev * HEv;
    const long hGT = (long)Bv * EEv, hT1 = (long)Bv * Hv * EEv, hT3 = (long)Bv * EHE;
    const long hq = (long)Bv * SE, hNT = (long)Bv * EEv;
    const long PART = (long)Bv * EEv;

    // fp32 prep
    colsum_kernel<<<Bv, Ev>>>(k, v, ksum, vsum);
    rowdot_kernel<<<2048, 256>>>(Wk, ksum, a);
    rowdot_kernel<<<2048, 256>>>(Wv, vsum, w);

    // conversions of inputs
    dim3 tb(32, 8);
    conv_tsplit<<<dim3(64, 16, Bv), tb>>>(k, kT, kT + hKT, Ev, SE, Sv, ES);
    conv_tsplit<<<dim3(64, 16, Bv), tb>>>(v, vT, vT + hKT, Ev, SE, Sv, ES);
    conv_tsplit<<<dim3(16, 16, Hv), tb>>>(Wq, bWqT, bWqT + hW, Ev, EE, Ev, EE);
    conv_split<<<2048, 256>>>(Wk, bWk, bWk + hW);
    conv_split<<<2048, 256>>>(Wv, bWv, bWv + hW);
    conv_split<<<2048, 256>>>(Wo, bWo, bWo + hWo);
    conv_split<<<4096, 256>>>(q, bq16, bq16 + hq);

    // 1) GT_b[e2][e1] = sum_s v[s][e2] k[s][e1]   (split-K=4 -> reduce to bf16)
    tgemm<0><<<dim3(4, 4, Bv * 4), 256, SMEM_DYN>>>(
        vT, vT + hKT, kT, kT + hKT, Tp, nullptr, nullptr, nullptr, nullptr, nullptr, nullptr,
        Sv, Ev, 1, 0, ES, 0, ES, 0, EE, 0, 4, PART);
    reduce4_hl<<<1024, 256>>>(Tp, PART, bGT, bGT + hGT);

    // 2) T1_z[o1][e2] = sum_e Wk[o1][e] GT[e2][e]   -> bf16 hi/lo direct
    tgemm<2><<<dim3(4, 4, Bv * Hv), 256, SMEM_DYN>>>(
        bWk, bWk + hW, bGT, bGT + hGT, bT1, bT1 + hT1, nullptr, nullptr, nullptr, nullptr, nullptr,
        Ev, Ev, Hv, EE, 0, 0, EE, EE, HEE, 0, 1, 0);

    // 3) MT_z[o2][o1] = sum_e2 Wv[o2][e2] T1[o1][e2]  -> fused rank-1 epilogue
    tgemm<3><<<dim3(4, 4, Bv * Hv), 256, SMEM_DYN>>>(
        bWv, bWv + hW, bT1, bT1 + hT1, M, bMT, bMT + hT1, a, w, bk, bv,
        Ev, Ev, Hv, EE, 0, EE, HEE, EE, HEE, 0, 1, 0);

    // 4) bias path (reads fp32 M)
    rcat_kernel<<<2048, 256>>>(bq, M, r);
    cvec_kernel<<<256, 256>>>(r, Wo, bo, c);

    // 5) T3_b[e][h*E+o2] = sum_o WqT[e][o] MT[o2][o]   -> bf16 hi/lo direct
    tgemm<2><<<dim3(4, 4, Bv * Hv), 256, SMEM_DYN>>>(
        bWqT, bWqT + hW, bMT, bMT + hT1, bT3, bT3 + hT3, nullptr, nullptr, nullptr, nullptr, nullptr,
        Ev, HEv, Hv, EE, 0, EE, HEE, (long)Ev, EHE, 0, 1, 0);

    // 6) NT_b[e2][e] = sum_f Wo[e2][f] T3[e][f]   (split-K=4 -> reduce to bf16)
    tgemm<0><<<dim3(4, 4, Bv * 4), 256, SMEM_DYN>>>(
        bWo, bWo + hWo, bT3, bT3 + hT3, Tp, nullptr, nullptr, nullptr, nullptr, nullptr, nullptr,
        HEv, Ev, 1, 0, 0, 0, EHE, 0, EE, 0, 4, PART);
    reduce4_hl<<<1024, 256>>>(Tp, PART, bNT, bNT + hNT);

    // 7) out_b[s][e2] = sum_e q[s][e] NT[e2][e] + c_b[e2]
    tgemm<1><<<dim3(4, 16, Bv), 256, SMEM_DYN>>>(
        bq16, bq16 + hq, bNT, bNT + hNT, out, c, nullptr, nullptr, nullptr, nullptr, nullptr,
        Ev, Ev, 1, 0, SE, 0, EE, 0, SE, (long)Ev, 1, 0);
}

// round 7
// speedup vs baseline: 2.4973x; 1.0301x over previous
#include <cuda_runtime.h>
#include <cuda_bf16.h>
#include <cstdint>

#define Bv 4
#define Sv 2048
#define Ev 512
#define Hv 8
#define HEv 4096
#define EEv 262144

// fp32 scratch
__device__ float g_T[(long)4 * Bv * EEv];      // split-K partials (16 MB)
__device__ float g_ksum[Bv * Ev], g_vsum[Bv * Ev];
__device__ float g_a[Bv * Hv * Ev], g_w[Bv * Hv * Ev];
__device__ float g_alpha[Bv * Hv * Ev], g_gamma[Hv * Ev];
__device__ float g_beta[Hv * Ev], g_delta[Bv * Hv * Ev];
__device__ float g_u[Hv * Ev], g_p[Bv * Hv * Ev], g_sigma[Bv * Hv * Ev];
__device__ float g_s1[Bv * Hv], g_s2[Hv];
__device__ float g_r[Bv * HEv], g_c[Bv * Ev];

// bf16 hi|lo buffers (lo at +half)
__device__ __nv_bfloat16 c_kT [2L * Bv * Ev * Sv];   // [b][e1][s]
__device__ __nv_bfloat16 c_vT [2L * Bv * Ev * Sv];   // [b][e2][s]
__device__ __nv_bfloat16 c_WqT[2L * Hv * EEv];       // [h][e][o1]
__device__ __nv_bfloat16 c_WkT[2L * Hv * EEv];       // [h][e1][o1]
__device__ __nv_bfloat16 c_WvT[2L * Hv * EEv];       // [h][e2][o2]
__device__ __nv_bfloat16 c_Wo [2L * Ev * HEv];       // [o3][f]
__device__ __nv_bfloat16 c_G  [2L * Bv * EEv];       // [b][e1][e2]
__device__ __nv_bfloat16 c_U  [2L * Ev * HEv];       // [e][h*E+e1]
__device__ __nv_bfloat16 c_V  [2L * Hv * EEv];       // [h][o3][e2]
__device__ __nv_bfloat16 c_X  [2L * Bv * Ev * HEv];  // [b][o3][h*E+e1]
__device__ __nv_bfloat16 c_q  [2L * Bv * Sv * Ev];   // [b][s][e]
__device__ __nv_bfloat16 c_NT [2L * Bv * EEv];       // [b][o3][e]

__device__ __forceinline__ uint32_t smem_u32(const void* p) {
    uint32_t a;
    asm("{ .reg .u64 t; cvta.to.shared.u64 t, %1; cvt.u32.u64 %0, t; }" : "=r"(a) : "l"(p));
    return a;
}
__device__ __forceinline__ void cpa16(uint32_t dst, const void* src) {
    asm volatile("cp.async.cg.shared.global [%0], [%1], 16;" :: "r"(dst), "l"(src));
}
__device__ __forceinline__ void ldsm4(uint32_t* r, uint32_t addr) {
    asm volatile("ldmatrix.sync.aligned.m8n8.x4.shared.b16 {%0,%1,%2,%3}, [%4];"
        : "=r"(r[0]), "=r"(r[1]), "=r"(r[2]), "=r"(r[3]) : "r"(addr));
}
__device__ __forceinline__ void mma_bf16(float* d, const uint32_t* a, const uint32_t* b) {
    asm volatile("mma.sync.aligned.m16n8k16.row.col.f32.bf16.bf16.f32 "
        "{%0,%1,%2,%3}, {%4,%5,%6,%7}, {%8,%9}, {%0,%1,%2,%3};"
        : "+f"(d[0]), "+f"(d[1]), "+f"(d[2]), "+f"(d[3])
        : "r"(a[0]), "r"(a[1]), "r"(a[2]), "r"(a[3]), "r"(b[0]), "r"(b[1]));
}
__device__ __forceinline__ __nv_bfloat162 hl_hi2(float x, float y) {
    __nv_bfloat162 r; r.x = __float2bfloat16(x); r.y = __float2bfloat16(y); return r;
}

#define STAGE 32768
#define SMEM_DYN (3 * STAGE)

// MODE: 0 = fp32 (split-K partials), 1 = fp32 + bias, 2 = bf16 hi/lo (aux = lo base)
// C(m,n) = sum_k A(m,k)*B(n,k); A,B bf16 row-major with strides lda/ldb, K % (64*nsplit) == 0.
// K tripled via hi/lo phases: [Ah*Bh, Ah*Bl, Al*Bh]. Tile 128x128, chunk 64, 3-stage pipe.
template <int MODE>
__global__ void __launch_bounds__(256, 2)
tgemm(const __nv_bfloat16* __restrict__ Ahi, const __nv_bfloat16* __restrict__ Alo,
      const __nv_bfloat16* __restrict__ Bhi, const __nv_bfloat16* __restrict__ Blo,
      void* __restrict__ Cout, const void* __restrict__ aux,
      int K, int lda, int ldb, int ldc, int zmod,
      long aS1, long aS2, long bS1, long bS2, long cS1, long cS2,
      long auxStride, int nsplit, long partStride)
{
    extern __shared__ __align__(128) char dsm[];
    uint32_t sbase = smem_u32(dsm);

    int tid = threadIdx.x, wid = tid >> 5, lane = tid & 31;
    int zPer = gridDim.z / nsplit;
    int split = blockIdx.z / zPer;
    int z = blockIdx.z % zPer;
    int zm = z % zmod, zd = z / zmod;
    Ahi += zm * aS1 + zd * aS2;  Alo += zm * aS1 + zd * aS2;
    Bhi += zm * bS1 + zd * bS2;  Blo += zm * bS1 + zd * bS2;
    int m0 = blockIdx.y * 128, n0 = blockIdx.x * 128;

    const int Ks = K / nsplit;
    const int CPP = Ks >> 6;
    const int NC = 3 * CPP;
    const int kofs = split * Ks;

    int srow = tid >> 3, scs = tid & 7;

    auto issue = [&](int c) {
        int phase = c / CPP;
        int kpos = kofs + ((c - phase * CPP) << 6);
        const __nv_bfloat16* pa = (phase < 2) ? Ahi : Alo;
        const __nv_bfloat16* pb = (phase == 1) ? Blo : Bhi;
        uint32_t sb = sbase + (uint32_t)((c % 3) * STAGE);
        #pragma unroll
        for (int t = 0; t < 8; t++) {
            int isB = t >> 2;
            int row = srow + ((t & 3) << 5);
            const __nv_bfloat16* src = isB
                ? pb + (long)(n0 + row) * ldb + kpos + (scs << 3)
                : pa + (long)(m0 + row) * lda + kpos + (scs << 3);
            uint32_t bo = (uint32_t)((row << 7) + (scs << 4));
            bo ^= (uint32_t)((row & 7) << 4);
            cpa16(sb + (uint32_t)(isB << 14) + bo, src);
        }
        asm volatile("cp.async.commit_group;" ::: "memory");
    };

    issue(0);
    issue(1);

    float acc[2][8][4] = {};
    int moff = (wid & 3) << 5;
    int noff = (wid >> 2) << 6;

    for (int c = 0; c < NC; c++) {
        if (c + 1 < NC) asm volatile("cp.async.wait_group 1;" ::: "memory");
        else            asm volatile("cp.async.wait_group 0;" ::: "memory");
        __syncthreads();
        if (c + 2 < NC) issue(c + 2);
        uint32_t sb = sbase + (uint32_t)((c % 3) * STAGE);

        #pragma unroll
        for (int ks = 0; ks < 4; ks++) {
            uint32_t afr[2][4];
            #pragma unroll
            for (int i = 0; i < 2; i++) {
                int row = moff + (i << 4) + (lane & 15);
                int colb = (ks << 5) + ((lane >> 4) << 4);
                uint32_t bo = (uint32_t)((row << 7) + colb) ^ (uint32_t)((row & 7) << 4);
                ldsm4(afr[i], sb + bo);
            }
            uint32_t bfr[8][2];
            #pragma unroll
            for (int j2 = 0; j2 < 4; j2++) {
                int row = noff + (j2 << 4) + ((lane >> 4) << 3) + (lane & 7);
                int colb = (ks << 5) + (((lane >> 3) & 1) << 4);
                uint32_t bo = (uint32_t)((row << 7) + colb) ^ (uint32_t)((row & 7) << 4);
                uint32_t r[4];
                ldsm4(r, sb + 16384u + bo);
                bfr[2 * j2][0] = r[0]; bfr[2 * j2][1] = r[1];
                bfr[2 * j2 + 1][0] = r[2]; bfr[2 * j2 + 1][1] = r[3];
            }
            #pragma unroll
            for (int i = 0; i < 2; i++)
                #pragma unroll
                for (int j = 0; j < 8; j++)
                    mma_bf16(acc[i][j], afr[i], bfr[j]);
        }
    }

    int g = lane >> 2, t4 = lane & 3;
    if (MODE == 2) {
        __nv_bfloat16* hi = (__nv_bfloat16*)Cout + zm * cS1 + zd * cS2;
        __nv_bfloat16* lo = (__nv_bfloat16*)aux  + zm * cS1 + zd * cS2;
        #pragma unroll
        for (int i = 0; i < 2; i++) {
            int row0 = m0 + moff + (i << 4) + g;
            #pragma unroll
            for (int j = 0; j < 8; j++) {
                int col = n0 + noff + (j << 3) + (t4 << 1);
                #pragma unroll
                for (int rr = 0; rr < 2; rr++) {
                    long off = (long)(row0 + 8 * rr) * ldc + col;
                    float vx = acc[i][j][2 * rr], vy = acc[i][j][2 * rr + 1];
                    __nv_bfloat162 h = hl_hi2(vx, vy);
                    __nv_bfloat162 l = hl_hi2(vx - __bfloat162float(h.x), vy - __bfloat162float(h.y));
                    *reinterpret_cast<__nv_bfloat162*>(hi + off) = h;
                    *reinterpret_cast<__nv_bfloat162*>(lo + off) = l;
                }
            }
        }
    } else {
        float* C = (float*)Cout + zm * cS1 + zd * cS2 + (long)split * partStride;
        const float* bp = (MODE == 1) ? ((const float*)aux + zd * auxStride) : nullptr;
        #pragma unroll
        for (int i = 0; i < 2; i++) {
            int row0 = m0 + moff + (i << 4) + g;
            #pragma unroll
            for (int j = 0; j < 8; j++) {
                int col = n0 + noff + (j << 3) + (t4 << 1);
                float bx = 0.f, by = 0.f;
                if (MODE == 1) { float2 bb = *reinterpret_cast<const float2*>(bp + col); bx = bb.x; by = bb.y; }
                float2 o0 = make_float2(acc[i][j][0] + bx, acc[i][j][1] + by);
                float2 o1 = make_float2(acc[i][j][2] + bx, acc[i][j][3] + by);
                *reinterpret_cast<float2*>(&C[(long)row0 * ldc + col]) = o0;
                *reinterpret_cast<float2*>(&C[(long)(row0 + 8) * ldc + col]) = o1;
            }
        }
    }
}

// sum 4 split-K partials -> bf16 hi/lo
__global__ void reduce4_hl(const float* __restrict__ parts, long pstride,
                           __nv_bfloat16* __restrict__ hi, __nv_bfloat16* __restrict__ lo) {
    long i = ((long)blockIdx.x * blockDim.x + threadIdx.x) * 4;
    float4 s = *reinterpret_cast<const float4*>(parts + i);
    #pragma unroll
    for (int p = 1; p < 4; p++) {
        float4 t = *reinterpret_cast<const float4*>(parts + p * pstride + i);
        s.x += t.x; s.y += t.y; s.z += t.z; s.w += t.w;
    }
    __nv_bfloat162 h0 = hl_hi2(s.x, s.y), h1 = hl_hi2(s.z, s.w);
    __nv_bfloat162 l0 = hl_hi2(s.x - __bfloat162float(h0.x), s.y - __bfloat162float(h0.y));
    __nv_bfloat162 l1 = hl_hi2(s.z - __bfloat162float(h1.x), s.w - __bfloat162float(h1.y));
    uint2 hp, lp;
    hp.x = *reinterpret_cast<uint32_t*>(&h0); hp.y = *reinterpret_cast<uint32_t*>(&h1);
    lp.x = *reinterpret_cast<uint32_t*>(&l0); lp.y = *reinterpret_cast<uint32_t*>(&l1);
    *reinterpret_cast<uint2*>(hi + i) = hp;
    *reinterpret_cast<uint2*>(lo + i) = lp;
}

// NT epilogue: NT = (sum partials + beta*(alpha + S*gamma) + delta*gamma) / E -> bf16 hi/lo
__global__ void nt_epilogue(const float* __restrict__ parts, long pstride,
                            const float* __restrict__ alpha, const float* __restrict__ gamma,
                            const float* __restrict__ beta, const float* __restrict__ delta,
                            __nv_bfloat16* __restrict__ hi, __nv_bfloat16* __restrict__ lo) {
    long i = ((long)blockIdx.x * blockDim.x + threadIdx.x) * 4;   // over Bv*EEv
    int e = (int)(i & 511);
    int o3 = (int)((i >> 9) & 511);
    int b = (int)(i >> 18);
    float4 s = *reinterpret_cast<const float4*>(parts + i);
    #pragma unroll
    for (int p = 1; p < 4; p++) {
        float4 t = *reinterpret_cast<const float4*>(parts + p * pstride + i);
        s.x += t.x; s.y += t.y; s.z += t.z; s.w += t.w;
    }
    #pragma unroll
    for (int h = 0; h < Hv; h++) {
        float be = beta[h * Ev + o3];
        float de = delta[(b * Hv + h) * Ev + o3];
        float4 al = *reinterpret_cast<const float4*>(alpha + (long)(b * Hv + h) * Ev + e);
        float4 ga = *reinterpret_cast<const float4*>(gamma + h * Ev + e);
        s.x += be * (al.x + (float)Sv * ga.x) + de * ga.x;
        s.y += be * (al.y + (float)Sv * ga.y) + de * ga.y;
        s.z += be * (al.z + (float)Sv * ga.z) + de * ga.z;
        s.w += be * (al.w + (float)Sv * ga.w) + de * ga.w;
    }
    const float invE = 1.0f / (float)Ev;
    s.x *= invE; s.y *= invE; s.z *= invE; s.w *= invE;
    __nv_bfloat162 h0 = hl_hi2(s.x, s.y), h1 = hl_hi2(s.z, s.w);
    __nv_bfloat162 l0 = hl_hi2(s.x - __bfloat162float(h0.x), s.y - __bfloat162float(h0.y));
    __nv_bfloat162 l1 = hl_hi2(s.z - __bfloat162float(h1.x), s.w - __bfloat162float(h1.y));
    uint2 hp, lp;
    hp.x = *reinterpret_cast<uint32_t*>(&h0); hp.y = *reinterpret_cast<uint32_t*>(&h1);
    lp.x = *reinterpret_cast<uint32_t*>(&l0); lp.y = *reinterpret_cast<uint32_t*>(&l1);
    *reinterpret_cast<uint2*>(hi + i) = hp;
    *reinterpret_cast<uint2*>(lo + i) = lp;
}

__global__ void conv_split(const float* __restrict__ src, __nv_bfloat16* __restrict__ hi,
                           __nv_bfloat16* __restrict__ lo) {
    long i = ((long)blockIdx.x * blockDim.x + threadIdx.x) * 4;
    float4 x = *reinterpret_cast<const float4*>(src + i);
    __nv_bfloat162 h0 = hl_hi2(x.x, x.y), h1 = hl_hi2(x.z, x.w);
    __nv_bfloat162 l0 = hl_hi2(x.x - __bfloat162float(h0.x), x.y - __bfloat162float(h0.y));
    __nv_bfloat162 l1 = hl_hi2(x.z - __bfloat162float(h1.x), x.w - __bfloat162float(h1.y));
    uint2 hp, lp;
    hp.x = *reinterpret_cast<uint32_t*>(&h0); hp.y = *reinterpret_cast<uint32_t*>(&h1);
    lp.x = *reinterpret_cast<uint32_t*>(&l0); lp.y = *reinterpret_cast<uint32_t*>(&l1);
    *reinterpret_cast<uint2*>(hi + i) = hp;
    *reinterpret_cast<uint2*>(lo + i) = lp;
}

__global__ void conv_tsplit(const float* __restrict__ src, __nv_bfloat16* __restrict__ hi,
                            __nv_bfloat16* __restrict__ lo,
                            int srcLd, long srcZ, int dstLd, long dstZ) {
    __shared__ float tile[32][33];
    int zz = blockIdx.z;
    src += (long)zz * srcZ;
    long dz = (long)zz * dstZ;
    int k0 = blockIdx.x * 32, r0 = blockIdx.y * 32;
    int tx = threadIdx.x, ty = threadIdx.y;
    #pragma unroll
    for (int i = 0; i < 4; i++)
        tile[ty + 8 * i][tx] = src[(long)(k0 + ty + 8 * i) * srcLd + r0 + tx];
    __syncthreads();
    #pragma unroll
    for (int i = 0; i < 4; i++) {
        int r = r0 + ty + 8 * i, kk = k0 + tx;
        float x = tile[tx][ty + 8 * i];
        __nv_bfloat16 h = __float2bfloat16(x);
        hi[dz + (long)r * dstLd + kk] = h;
        lo[dz + (long)r * dstLd + kk] = __float2bfloat16(x - __bfloat162float(h));
    }
}

__global__ void colsum_kernel(const float* __restrict__ k, const float* __restrict__ v,
                              float* __restrict__ ks, float* __restrict__ vs) {
    int b = blockIdx.x, e = threadIdx.x;
    const float* kb = k + (long)b * Sv * Ev;
    const float* vb = v + (long)b * Sv * Ev;
    float sk = 0.f, sv = 0.f;
    for (int s = 0; s < Sv; s++) { sk += kb[(long)s * Ev + e]; sv += vb[(long)s * Ev + e]; }
    ks[b * Ev + e] = sk; vs[b * Ev + e] = sv;
}

// out[z*E + o] = dot(W[(z%8)*E + o, :], x[xsel ? z : z>>3, :]) over E, fp32 W rows.
__global__ void rowdot_kernel(const float* __restrict__ W, const float* __restrict__ x,
                              float* __restrict__ out, int xsel) {
    int gw = (blockIdx.x * blockDim.x + threadIdx.x) >> 5, lane = threadIdx.x & 31;
    int o = gw & (Ev - 1), zz = gw >> 9;
    int h = zz & (Hv - 1);
    const float* wr = W + (long)(h * Ev + o) * Ev;
    const float* xr = x + (long)(xsel ? zz : (zz >> 3)) * Ev;
    float s = 0.f;
    for (int e = lane; e < Ev; e += 32) s += wr[e] * xr[e];
    #pragma unroll
    for (int off = 16; off > 0; off >>= 1) s += __shfl_xor_sync(0xFFFFFFFFu, s, off);
    if (lane == 0) out[gw] = s;
}

// out[z*E + e] = dot over E of (hi+lo)[(z%8)*EE + e*E + :] . x[z*E + :]
__global__ void rowdot_hl(const __nv_bfloat16* __restrict__ Whi, const __nv_bfloat16* __restrict__ Wlo,
                          const float* __restrict__ x, float* __restrict__ out) {
    int gw = (blockIdx.x * blockDim.x + threadIdx.x) >> 5, lane = threadIdx.x & 31;
    int e = gw & (Ev - 1), zz = gw >> 9;
    long wofs = (long)(zz & (Hv - 1)) * EEv + (long)e * Ev;
    const float* xr = x + (long)zz * Ev;
    float s = 0.f;
    for (int o = lane; o < Ev; o += 32)
        s += (__bfloat162float(Whi[wofs + o]) + __bfloat162float(Wlo[wofs + o])) * xr[o];
    #pragma unroll
    for (int off = 16; off > 0; off >>= 1) s += __shfl_xor_sync(0xFFFFFFFFu, s, off);
    if (lane == 0) out[gw] = s;
}

// out[z*E + o3] = dot over E of Wo[o3*HE + (z%8)*E + :] . x[z*E + :]
__global__ void rowdot_wo(const float* __restrict__ Wo, const float* __restrict__ x,
                          float* __restrict__ out) {
    int gw = (blockIdx.x * blockDim.x + threadIdx.x) >> 5, lane = threadIdx.x & 31;
    int o3 = gw & (Ev - 1), zz = gw >> 9;
    const float* wr = Wo + (long)o3 * HEv + (long)(zz & (Hv - 1)) * Ev;
    const float* xr = x + (long)zz * Ev;
    float s = 0.f;
    for (int e = lane; e < Ev; e += 32) s += wr[e] * xr[e];
    #pragma unroll
    for (int off = 16; off > 0; off >>= 1) s += __shfl_xor_sync(0xFFFFFFFFu, s, off);
    if (lane == 0) out[gw] = s;
}

// p[z*E + e2] = sum_e1 u[(z%8)*E + e1] * G[(z>>3)][e1][e2]  (G from hi+lo bf16)
__global__ void colmv_kernel(const __nv_bfloat16* __restrict__ Ghi, const __nv_bfloat16* __restrict__ Glo,
                             const float* __restrict__ u, float* __restrict__ p) {
    int zz = blockIdx.x, tid = threadIdx.x;
    int b = zz >> 3, h = zz & (Hv - 1);
    __shared__ float us[Ev];
    us[tid] = u[h * Ev + tid];
    __syncthreads();
    const __nv_bfloat16* gh = Ghi + (long)b * EEv;
    const __nv_bfloat16* gl = Glo + (long)b * EEv;
    float acc = 0.f;
    #pragma unroll 4
    for (int e1 = 0; e1 < Ev; e1++) {
        long idx = (long)e1 * Ev + tid;
        acc += us[e1] * (__bfloat162float(gh[idx]) + __bfloat162float(gl[idx]));
    }
    p[(long)zz * Ev + tid] = acc;
}

// s1[z] = bq_h . a_z (z<32, h=z%8); s2[h] = bq_h . bk_h (gw in [32,40))
__global__ void dots_kernel(const float* __restrict__ bq, const float* __restrict__ a,
                            const float* __restrict__ bk,
                            float* __restrict__ s1, float* __restrict__ s2) {
    int gw = (blockIdx.x * blockDim.x + threadIdx.x) >> 5, lane = threadIdx.x & 31;
    if (gw >= 40) return;
    const float* xa;
    const float* xb;
    if (gw < 32) { xa = bq + (gw & 7) * Ev; xb = a + gw * Ev; }
    else         { xa = bq + (gw - 32) * Ev; xb = bk + (gw - 32) * Ev; }
    float s = 0.f;
    for (int o = lane; o < Ev; o += 32) s += xa[o] * xb[o];
    #pragma unroll
    for (int off = 16; off > 0; off >>= 1) s += __shfl_xor_sync(0xFFFFFFFFu, s, off);
    if (lane == 0) { if (gw < 32) s1[gw] = s; else s2[gw - 32] = s; }
}

// tau[z*E+o2] = sigma + s1[z]*bv[h,o2] + s2[h]*(w[z,o2] + S*bv[h,o2])
__global__ void tau_kernel(const float* __restrict__ sigma, const float* __restrict__ s1,
                           const float* __restrict__ s2, const float* __restrict__ bv,
                           const float* __restrict__ w, float* __restrict__ tau) {
    int idx = blockIdx.x * blockDim.x + threadIdx.x;     // < 16384
    int zz = idx >> 9, o2 = idx & (Ev - 1), h = zz & (Hv - 1);
    float bvv = bv[h * Ev + o2];
    tau[idx] = sigma[idx] + s1[zz] * bvv + s2[h] * (w[idx] + (float)Sv * bvv);
}

// c[b*E+o3] = bo[o3] + (1/E) * dot(Wo[o3][:], tau[b][:])
__global__ void cvec_kernel(const float* __restrict__ r, const float* __restrict__ Wo,
                            const float* __restrict__ bo, float* __restrict__ c) {
    int gw = (blockIdx.x * blockDim.x + threadIdx.x) >> 5, lane = threadIdx.x & 31;
    int e2 = gw & (Ev - 1), b = gw >> 9;
    const float* rr = r + (long)b * HEv;
    const float* wr = Wo + (long)e2 * HEv;
    float s = 0.f;
    for (int f = lane; f < HEv; f += 32) s += rr[f] * wr[f];
    #pragma unroll
    for (int off = 16; off > 0; off >>= 1) s += __shfl_xor_sync(0xFFFFFFFFu, s, off);
    if (lane == 0) c[gw] = s * (1.0f / (float)Ev) + bo[e2];
}

extern "C" void kernel_launch(void* const* d_in, const int* in_sizes, int n_in,
                              void* d_out, int out_size) {
    const float* q  = (const float*)d_in[0];
    const float* k  = (const float*)d_in[1];
    const float* v  = (const float*)d_in[2];
    const float* Wq = (const float*)d_in[3];
    const float* bq = (const float*)d_in[4];
    const float* Wk = (const float*)d_in[5];
    const float* bk = (const float*)d_in[6];
    const float* Wv = (const float*)d_in[7];
    const float* bv = (const float*)d_in[8];
    const float* Wo = (const float*)d_in[9];
    const float* bo = (const float*)d_in[10];
    float* out = (float*)d_out;

    float *Tp, *ksum, *vsum, *a, *w, *alpha, *gamma, *beta, *delta, *u, *p, *sigma, *s1, *s2, *r, *c;
    cudaGetSymbolAddress((void**)&Tp, g_T);
    cudaGetSymbolAddress((void**)&ksum, g_ksum);
    cudaGetSymbolAddress((void**)&vsum, g_vsum);
    cudaGetSymbolAddress((void**)&a, g_a);
    cudaGetSymbolAddress((void**)&w, g_w);
    cudaGetSymbolAddress((void**)&alpha, g_alpha);
    cudaGetSymbolAddress((void**)&gamma, g_gamma);
    cudaGetSymbolAddress((void**)&beta, g_beta);
    cudaGetSymbolAddress((void**)&delta, g_delta);
    cudaGetSymbolAddress((void**)&u, g_u);
    cudaGetSymbolAddress((void**)&p, g_p);
    cudaGetSymbolAddress((void**)&sigma, g_sigma);
    cudaGetSymbolAddress((void**)&s1, g_s1);
    cudaGetSymbolAddress((void**)&s2, g_s2);
    cudaGetSymbolAddress((void**)&r, g_r);
    cudaGetSymbolAddress((void**)&c, g_c);

    __nv_bfloat16 *kT, *vT, *bWqT, *bWkT, *bWvT, *bWo, *bG, *bU, *bV, *bX, *bq16, *bNT;
    cudaGetSymbolAddress((void**)&kT, c_kT);
    cudaGetSymbolAddress((void**)&vT, c_vT);
    cudaGetSymbolAddress((void**)&bWqT, c_WqT);
    cudaGetSymbolAddress((void**)&bWkT, c_WkT);
    cudaGetSymbolAddress((void**)&bWvT, c_WvT);
    cudaGetSymbolAddress((void**)&bWo, c_Wo);
    cudaGetSymbolAddress((void**)&bG, c_G);
    cudaGetSymbolAddress((void**)&bU, c_U);
    cudaGetSymbolAddress((void**)&bV, c_V);
    cudaGetSymbolAddress((void**)&bX, c_X);
    cudaGetSymbolAddress((void**)&bq16, c_q);
    cudaGetSymbolAddress((void**)&bNT, c_NT);

    cudaFuncSetAttribute(tgemm<0>, cudaFuncAttributeMaxDynamicSharedMemorySize, SMEM_DYN);
    cudaFuncSetAttribute(tgemm<1>, cudaFuncAttributeMaxDynamicSharedMemorySize, SMEM_DYN);
    cudaFuncSetAttribute(tgemm<2>, cudaFuncAttributeMaxDynamicSharedMemorySize, SMEM_DYN);

    const long ES = (long)Ev * Sv, EE = EEv, SE = (long)Sv * Ev, EHE = (long)Ev * HEv;
    const long hKT = (long)Bv * ES, hW = (long)Hv * EEv, hWo = (long)Ev * HEv;
    const long hG = (long)Bv * EEv, hU = (long)Ev * HEv, hV = (long)Hv * EEv;
    const long hX = (long)Bv * Ev * HEv, hq = (long)Bv * SE, hNT = (long)Bv * EEv;
    const long PART = (long)Bv * EEv;   // split-K partial stride (1M floats)

    // prep + conversions
    colsum_kernel<<<Bv, Ev>>>(k, v, ksum, vsum);
    rowdot_kernel<<<2048, 256>>>(Wk, ksum, a, 0);
    rowdot_kernel<<<2048, 256>>>(Wv, vsum, w, 0);
    dim3 tb(32, 8);
    conv_tsplit<<<dim3(64, 16, Bv), tb>>>(k, kT, kT + hKT, Ev, SE, Sv, ES);
    conv_tsplit<<<dim3(64, 16, Bv), tb>>>(v, vT, vT + hKT, Ev, SE, Sv, ES);
    conv_tsplit<<<dim3(16, 16, Hv), tb>>>(Wq, bWqT, bWqT + hW, Ev, EE, Ev, EE);
    conv_tsplit<<<dim3(16, 16, Hv), tb>>>(Wk, bWkT, bWkT + hW, Ev, EE, Ev, EE);
    conv_tsplit<<<dim3(16, 16, Hv), tb>>>(Wv, bWvT, bWvT + hW, Ev, EE, Ev, EE);
    conv_split<<<2048, 256>>>(Wo, bWo, bWo + hWo);
    conv_split<<<4096, 256>>>(q, bq16, bq16 + hq);

    // 1) G_b[e1][e2] = sum_s k[s][e1] v[s][e2]   split-K=4 -> bf16 hi/lo
    tgemm<0><<<dim3(4, 4, Bv * 4), 256, SMEM_DYN>>>(
        kT, kT + hKT, vT, vT + hKT, Tp, nullptr,
        Sv, Sv, Sv, Ev, 1, 0, ES, 0, ES, 0, EE, 0, 4, PART);
    reduce4_hl<<<1024, 256>>>(Tp, PART, bG, bG + hG);

    // 2) Ucat[e][h*E+e1] = Wq_h^T Wk_h   (batch h only)
    tgemm<2><<<dim3(4, 4, Hv), 256, SMEM_DYN>>>(
        bWqT, bWqT + hW, bWkT, bWkT + hW, bU, bU + hU,
        Ev, Ev, Ev, HEv, Hv, EE, 0, EE, 0, (long)Ev, 0, 0, 1, 0);

    // 3) V_h[o3][e2] = Wo_h Wv_h
    tgemm<2><<<dim3(4, 4, Hv), 256, SMEM_DYN>>>(
        bWo, bWo + hWo, bWvT, bWvT + hW, bV, bV + hV,
        Ev, HEv, Ev, Ev, Hv, (long)Ev, 0, EE, 0, EE, 0, 0, 1, 0);

    // 4) XTcat[b][o3][h*E+e1] = V_h G_b^T (rows o3, k=e2)
    tgemm<2><<<dim3(4, 4, Bv * Hv), 256, SMEM_DYN>>>(
        bV, bV + hV, bG, bG + hG, bX, bX + hX,
        Ev, Ev, Ev, HEv, Hv, EE, 0, 0, EE, (long)Ev, EHE, 0, 1, 0);

    // 5) bias-path small kernels (need bG, bWqT, bWkT)
    rowdot_hl<<<2048, 256>>>(bWqT, bWqT + hW, a, alpha);     // alpha[b*8+h][e]
    rowdot_hl<<<512, 256>>>(bWqT, bWqT + hW, bk, gamma);     // gamma[h][e]
    rowdot_hl<<<512, 256>>>(bWkT, bWkT + hW, bq, u);         // u[h][e1]
    rowdot_wo<<<512, 256>>>(Wo, bv, beta);                   // beta[h][o3]
    rowdot_wo<<<2048, 256>>>(Wo, w, delta);                  // delta[b*8+h][o3]
    colmv_kernel<<<Bv * Hv, Ev>>>(bG, bG + hG, u, p);        // p[b*8+h][e2]
    rowdot_kernel<<<2048, 256>>>(Wv, p, sigma, 1);           // sigma[b*8+h][o2]
    dots_kernel<<<5, 256>>>(bq, a, bk, s1, s2);
    tau_kernel<<<64, 256>>>(sigma, s1, s2, bv, w, r);        // tau -> r[b][h*E+o2]
    cvec_kernel<<<256, 256>>>(r, Wo, bo, c);

    // 6) NT_b[o3][e] = sum_f XTcat[b][o3][f] Ucat[e][f]   K=4096, split-K=4
    tgemm<0><<<dim3(4, 4, Bv * 4), 256, SMEM_DYN>>>(
        bX, bX + hX, bU, bU + hU, Tp, nullptr,
        HEv, HEv, HEv, Ev, 1, 0, EHE, 0, 0, 0, EE, 0, 4, PART);
    nt_epilogue<<<1024, 256>>>(Tp, PART, alpha, gamma, beta, delta, bNT, bNT + hNT);

    // 7) out_b[s][o3] = sum_e q[s][e] NT[o3][e] + c_b[o3]
    tgemm<1><<<dim3(4, 16, Bv), 256, SMEM_DYN>>>(
        bq16, bq16 + hq, bNT, bNT + hNT, out, c,
        Ev, Ev, Ev, Ev, 1, 0, SE, 0, EE, 0, SE, (long)Ev, 1, 0);
}